// round 8
// baseline (speedup 1.0000x reference)
#include <cuda_runtime.h>

// ---------------- problem constants ----------------
#define BB      32
#define NN      64
#define FA      82
#define FP      102
#define HH      8
#define DKK     80
#define HID     256
#define HB      (HH*BB)        // 256
#define ROWS    (BB*NN)        // 2048
#define PAIRS   (BB*NN*NN)     // 131072
#define CATK    722
#define CATS    724            // padded row stride for concat matrix

// ---------------- device scratch (no allocations allowed) ----------------
__device__ float g_P[(size_t)PAIRS*DKK];      // path @ W1p + b_attn_h   [b,i,j,d]
__device__ float g_Q[(size_t)PAIRS*DKK];      // path @ W2p              [b,i,j,d]
__device__ float g_atom0[(size_t)HB*NN*DKK];  // atom_h0 [h*B+b, n, d]
__device__ float g_atomh[(size_t)HB*NN*DKK];  // current atom_h
__device__ float g_u [(size_t)HB*NN*DKK];     // atomh @ W1a
__device__ float g_v [(size_t)HB*NN*DKK];     // atomh @ W1b
__device__ float g_ws[(size_t)HB*NN*DKK];     // atomh @ W2a (self part of msg)
__device__ float g_w [(size_t)HB*NN*DKK];     // atomh @ W2b
__device__ float g_cat[(size_t)ROWS*CATS];    // [atom_input | merged heads]

// ============================================================
// Kernel A: atom_h0 = atom_input @ W_atom_i  (and init g_atomh, g_cat[:, :82])
// grid (32, 8): 64 rows x 80 cols per CTA, 256 threads
// ============================================================
__global__ void __launch_bounds__(256) k_proj0(const float* __restrict__ atom,
                                               const float* __restrict__ Wai) {
    __shared__ float As[64*FA];   // 64x82
    __shared__ float Bs[FA*DKK];  // 82x80
    const int tid = threadIdx.x;
    const int r0 = blockIdx.x * 64;
    const int h  = blockIdx.y;          // head = column block
    const int c0 = h * DKK;

    for (int i = tid; i < 64*FA; i += 256) As[i] = atom[(size_t)r0*FA + i];
    for (int i = tid; i < FA*DKK; i += 256) {
        int k = i / DKK, c = i % DKK;
        Bs[i] = Wai[(size_t)k*(HH*DKK) + c0 + c];
    }
    __syncthreads();

    const int ty = tid >> 4, tx = tid & 15;
    float acc[4][5];
#pragma unroll
    for (int r = 0; r < 4; r++)
#pragma unroll
        for (int c = 0; c < 5; c++) acc[r][c] = 0.f;

    for (int k = 0; k < FA; k++) {
        float a[4], b[5];
#pragma unroll
        for (int r = 0; r < 4; r++) a[r] = As[(ty*4+r)*FA + k];
#pragma unroll
        for (int c = 0; c < 5; c++) b[c] = Bs[k*DKK + tx*5 + c];
#pragma unroll
        for (int r = 0; r < 4; r++)
#pragma unroll
            for (int c = 0; c < 5; c++) acc[r][c] += a[r]*b[c];
    }

#pragma unroll
    for (int r = 0; r < 4; r++) {
        int row = r0 + ty*4 + r;
#pragma unroll
        for (int c = 0; c < 5; c++) {
            int d = tx*5 + c;
            size_t o = ((size_t)h*ROWS + row)*DKK + d;
            g_atom0[o] = acc[r][c];
            g_atomh[o] = acc[r][c];
        }
    }
    if (blockIdx.y == 0) {  // copy atom_input into concat matrix
        for (int i = tid; i < 64*FA; i += 256)
            g_cat[(size_t)(r0 + i/FA)*CATS + (i % FA)] = As[i];
    }
}

// ============================================================
// Kernel B: [P|Q] = path[131072,102] @ [W1p|W2p][102,160]  (+ b_attn_h on P)
// grid 1024: 128 rows x 160 cols per CTA, 256 threads, dynamic smem
// ============================================================
__global__ void __launch_bounds__(256) k_pathproj(const float* __restrict__ path,
                                                  const float* __restrict__ Wah,
                                                  const float* __restrict__ Wmh,
                                                  const float* __restrict__ bah) {
    extern __shared__ float sm[];
    float* As = sm;               // [128][102]
    float* Bs = sm + 128*FP;      // [102][160]
    const int tid = threadIdx.x;
    const size_t r0 = (size_t)blockIdx.x * 128;

    {   // A tile is a contiguous chunk of path -> linear float4 copy
        const float4* src = reinterpret_cast<const float4*>(path + r0*FP);
        float4* dst = reinterpret_cast<float4*>(As);
        for (int i = tid; i < 128*FP/4; i += 256) dst[i] = src[i];
    }
    for (int i = tid; i < FP*160; i += 256) {
        int k = i / 160, c = i % 160;
        Bs[i] = (c < DKK) ? Wah[(size_t)(160+k)*DKK + c]
                          : Wmh[(size_t)(160+k)*DKK + (c - DKK)];
    }
    __syncthreads();

    const int ty = tid >> 4, tx = tid & 15;   // 8 rows x 10 cols per thread
    float acc[8][10];
#pragma unroll
    for (int r = 0; r < 8; r++)
#pragma unroll
        for (int c = 0; c < 10; c++) acc[r][c] = 0.f;

    for (int k = 0; k < FP; k++) {
        float a[8], b[10];
#pragma unroll
        for (int r = 0; r < 8; r++) a[r] = As[(ty*8+r)*FP + k];
        const float2* bp = reinterpret_cast<const float2*>(Bs + k*160 + tx*10);
#pragma unroll
        for (int c = 0; c < 5; c++) { float2 t = bp[c]; b[2*c] = t.x; b[2*c+1] = t.y; }
#pragma unroll
        for (int r = 0; r < 8; r++)
#pragma unroll
            for (int c = 0; c < 10; c++) acc[r][c] += a[r]*b[c];
    }

#pragma unroll
    for (int r = 0; r < 8; r++) {
        size_t row = r0 + ty*8 + r;
#pragma unroll
        for (int c = 0; c < 10; c++) {
            int col = tx*10 + c;
            if (col < DKK) g_P[row*DKK + col] = acc[r][c] + bah[col];
            else           g_Q[row*DKK + (col - DKK)] = acc[r][c];
        }
    }
}

// ============================================================
// Kernel P: {u, v, ws, w} = g_atomh[16384,80] @ [W1a|W1b|W2a|W2b][80,320]
// grid (128, 2): 128 rows x 160 cols per CTA, 256 threads, dynamic smem
// ============================================================
__global__ void __launch_bounds__(256) k_proj4(const float* __restrict__ Wah,
                                               const float* __restrict__ Wmh) {
    extern __shared__ float sm[];
    float* As = sm;               // [128][80]
    float* Bs = sm + 128*DKK;     // [80][160]
    const int tid = threadIdx.x;
    const size_t r0 = (size_t)blockIdx.x * 128;
    const int c0 = blockIdx.y * 160;

    {
        const float4* src = reinterpret_cast<const float4*>(g_atomh + r0*DKK);
        float4* dst = reinterpret_cast<float4*>(As);
        for (int i = tid; i < 128*DKK/4; i += 256) dst[i] = src[i];
    }
    for (int i = tid; i < DKK*160; i += 256) {
        int k = i / 160, c = i % 160;
        int cg = c0 + c;
        float v;
        if      (cg <  80) v = Wah[(size_t)k*DKK + cg];            // W1a -> u
        else if (cg < 160) v = Wah[(size_t)(80+k)*DKK + cg - 80];  // W1b -> v
        else if (cg < 240) v = Wmh[(size_t)k*DKK + cg - 160];      // W2a -> ws
        else               v = Wmh[(size_t)(80+k)*DKK + cg - 240]; // W2b -> w
        Bs[i] = v;
    }
    __syncthreads();

    const int ty = tid >> 4, tx = tid & 15;
    float acc[8][10];
#pragma unroll
    for (int r = 0; r < 8; r++)
#pragma unroll
        for (int c = 0; c < 10; c++) acc[r][c] = 0.f;

    for (int k = 0; k < DKK; k++) {
        float a[8], b[10];
#pragma unroll
        for (int r = 0; r < 8; r++) a[r] = As[(ty*8+r)*DKK + k];
        const float2* bp = reinterpret_cast<const float2*>(Bs + k*160 + tx*10);
#pragma unroll
        for (int c = 0; c < 5; c++) { float2 t = bp[c]; b[2*c] = t.x; b[2*c+1] = t.y; }
#pragma unroll
        for (int r = 0; r < 8; r++)
#pragma unroll
            for (int c = 0; c < 10; c++) acc[r][c] += a[r]*b[c];
    }

    // FIXED scatter: cg & 79 != cg % 80 (79 = 0b1001111 zeroes bits 16/32).
    // Compute the true per-matrix column offset explicitly.
#pragma unroll
    for (int r = 0; r < 8; r++) {
        size_t row = r0 + ty*8 + r;
#pragma unroll
        for (int c = 0; c < 10; c++) {
            int cg = c0 + tx*10 + c;
            float* dstp; int cc;
            if      (cg <  80) { dstp = g_u;  cc = cg;       }
            else if (cg < 160) { dstp = g_v;  cc = cg - 80;  }
            else if (cg < 240) { dstp = g_ws; cc = cg - 160; }
            else               { dstp = g_w;  cc = cg - 240; }
            dstp[row*DKK + cc] = acc[r][c];
        }
    }
}

// ============================================================
// Kernel C: one message-passing layer. CTA = (b,i), warp = head.
// hidden = lrelu(u_i + v_j + P_ij); score = (hidden.Wo + bo)*mask
// softmax over j; acc = sum_j p_j (w_j + Q_ij); new = relu(S*ws_i + acc + bmsg + atom0)
// ============================================================
__global__ void __launch_bounds__(256) k_attn(const float* __restrict__ mask,
                                              const float* __restrict__ Wo,
                                              const float* __restrict__ bo,
                                              const float* __restrict__ bmsg,
                                              int mode) {
    __shared__ float sP[NN*DKK];
    __shared__ float sQ[NN*DKK];
    __shared__ float sSc[HH*NN];
    __shared__ float sPr[HH*NN];
    __shared__ float sM[NN];

    const int tid = threadIdx.x;
    const int bi = blockIdx.x;
    const int b = bi >> 6, i = bi & 63;
    (void)i;

    {
        const float4* ps = reinterpret_cast<const float4*>(g_P + (size_t)bi*NN*DKK);
        const float4* qs = reinterpret_cast<const float4*>(g_Q + (size_t)bi*NN*DKK);
        float4* pd = reinterpret_cast<float4*>(sP);
        float4* qd = reinterpret_cast<float4*>(sQ);
        for (int t = tid; t < NN*DKK/4; t += 256) { pd[t] = ps[t]; qd[t] = qs[t]; }
    }
    if (tid < NN) sM[tid] = mask[(size_t)bi*NN + tid];
    __syncthreads();

    const int h = tid >> 5, lane = tid & 31;
    const int hb = h*BB + b;
    const size_t base_i = ((size_t)hb*NN + (bi & 63))*DKK;

    const float* urow = g_u + base_i;
    const float u0 = urow[lane], u1 = urow[lane+32];
    const float u2 = (lane < 16) ? urow[64+lane] : 0.f;
    const float w0 = Wo[lane], w1 = Wo[lane+32];
    const float w2 = (lane < 16) ? Wo[64+lane] : 0.f;

    const float* V = g_v + (size_t)hb*NN*DKK;
    float* sc = sSc + h*NN;

    // ---- pass 1: scores (skip masked j — score is exactly 0 there) ----
    for (int j = 0; j < NN; j++) {
        if (sM[j] == 0.f) { if (lane == 0) sc[j] = 0.f; continue; }
        const float* vr = V + (size_t)j*DKK;
        float h0 = u0 + vr[lane]    + sP[j*DKK + lane];
        float h1 = u1 + vr[lane+32] + sP[j*DKK + 32 + lane];
        float h2 = 0.f;
        if (lane < 16) h2 = u2 + vr[64+lane] + sP[j*DKK + 64 + lane];
        h0 = h0 > 0.f ? h0 : 0.2f*h0;
        h1 = h1 > 0.f ? h1 : 0.2f*h1;
        h2 = h2 > 0.f ? h2 : 0.2f*h2;
        float s = h0*w0 + h1*w1 + h2*w2;
        s += __shfl_xor_sync(0xffffffffu, s, 16);
        s += __shfl_xor_sync(0xffffffffu, s, 8);
        s += __shfl_xor_sync(0xffffffffu, s, 4);
        s += __shfl_xor_sync(0xffffffffu, s, 2);
        s += __shfl_xor_sync(0xffffffffu, s, 1);
        if (lane == 0) sc[j] = s;
    }
    __syncwarp();

    // ---- masked softmax over j (per warp, each lane owns j=lane, j=lane+32) ----
    const float bov = bo[0];
    const float m0 = sM[lane], m1 = sM[lane+32];
    float s0 = (sc[lane]    + bov) * m0;
    float s1 = (sc[lane+32] + bov) * m1;
    float mx = fmaxf(s0, s1);
    mx = fmaxf(mx, __shfl_xor_sync(0xffffffffu, mx, 16));
    mx = fmaxf(mx, __shfl_xor_sync(0xffffffffu, mx, 8));
    mx = fmaxf(mx, __shfl_xor_sync(0xffffffffu, mx, 4));
    mx = fmaxf(mx, __shfl_xor_sync(0xffffffffu, mx, 2));
    mx = fmaxf(mx, __shfl_xor_sync(0xffffffffu, mx, 1));
    float e0 = __expf(s0 - mx) * m0;
    float e1 = __expf(s1 - mx) * m1;
    float tot = e0 + e1;
    tot += __shfl_xor_sync(0xffffffffu, tot, 16);
    tot += __shfl_xor_sync(0xffffffffu, tot, 8);
    tot += __shfl_xor_sync(0xffffffffu, tot, 4);
    tot += __shfl_xor_sync(0xffffffffu, tot, 2);
    tot += __shfl_xor_sync(0xffffffffu, tot, 1);
    const float inv = 1.f / (tot + 1e-20f);
    sPr[h*NN + lane]      = e0 * inv;   // mask is binary; e already carries it
    sPr[h*NN + lane + 32] = e1 * inv;
    const float S = tot * inv;          // sum_j probs_j
    __syncwarp();

    // ---- pass 2: weighted message accumulation (skip p == 0 exactly) ----
    const float* W_ = g_w + (size_t)hb*NN*DKK;
    const float* pr = sPr + h*NN;
    float a0 = 0.f, a1 = 0.f, a2 = 0.f;
    for (int j = 0; j < NN; j++) {
        float p = pr[j];
        if (p == 0.f) continue;
        const float* wr = W_ + (size_t)j*DKK;
        a0 += p * (wr[lane]    + sQ[j*DKK + lane]);
        a1 += p * (wr[lane+32] + sQ[j*DKK + 32 + lane]);
        if (lane < 16) a2 += p * (wr[64+lane] + sQ[j*DKK + 64 + lane]);
    }

    const float* wsr = g_ws   + base_i;
    const float* a0r = g_atom0 + base_i;
    float n0 = fmaxf(S*wsr[lane]    + a0 + bmsg[lane]    + a0r[lane],    0.f);
    float n1 = fmaxf(S*wsr[lane+32] + a1 + bmsg[lane+32] + a0r[lane+32], 0.f);
    float n2 = 0.f;
    if (lane < 16) n2 = fmaxf(S*wsr[64+lane] + a2 + bmsg[64+lane] + a0r[64+lane], 0.f);

    if (mode == 0) {
        float* o = g_atomh + base_i;
        o[lane] = n0; o[lane+32] = n1; if (lane < 16) o[64+lane] = n2;
    } else {
        float* o = g_cat + (size_t)bi*CATS + FA + h*DKK;   // merged-head layout
        o[lane] = n0; o[lane+32] = n1; if (lane < 16) o[64+lane] = n2;
    }
}

// ============================================================
// Kernel E: out = relu(g_cat[2048,722] @ W_atom_o[722,256] + b)
// grid (32, 4): 64 rows x 64 cols per CTA, 256 threads, K-chunks of 64
// ============================================================
__global__ void __launch_bounds__(256) k_final(const float* __restrict__ Wao,
                                               const float* __restrict__ bao,
                                               float* __restrict__ out) {
    __shared__ float As[64*64];
    __shared__ float Bs[64*64];
    const int tid = threadIdx.x;
    const int r0 = blockIdx.x * 64;
    const int c0 = blockIdx.y * 64;
    const int ty = tid >> 4, tx = tid & 15;

    float acc[4][4];
#pragma unroll
    for (int r = 0; r < 4; r++)
#pragma unroll
        for (int c = 0; c < 4; c++) acc[r][c] = 0.f;

    for (int k0 = 0; k0 < CATK; k0 += 64) {
        const int kc = (CATK - k0 < 64) ? (CATK - k0) : 64;
        for (int t = tid; t < 64*64; t += 256) {
            int r = t >> 6, k = t & 63;
            As[t] = (k < kc) ? g_cat[(size_t)(r0 + r)*CATS + k0 + k] : 0.f;
        }
        for (int t = tid; t < 64*64; t += 256) {
            int k = t >> 6, c = t & 63;
            Bs[t] = (k < kc) ? Wao[(size_t)(k0 + k)*HID + c0 + c] : 0.f;
        }
        __syncthreads();
#pragma unroll 8
        for (int k = 0; k < 64; k++) {
            float a[4], b[4];
#pragma unroll
            for (int r = 0; r < 4; r++) a[r] = As[(ty*4+r)*64 + k];
#pragma unroll
            for (int c = 0; c < 4; c++) b[c] = Bs[k*64 + tx*4 + c];
#pragma unroll
            for (int r = 0; r < 4; r++)
#pragma unroll
                for (int c = 0; c < 4; c++) acc[r][c] += a[r]*b[c];
        }
        __syncthreads();
    }

#pragma unroll
    for (int r = 0; r < 4; r++) {
        int row = r0 + ty*4 + r;
#pragma unroll
        for (int c = 0; c < 4; c++) {
            int col = c0 + tx*4 + c;
            out[(size_t)row*HID + col] = fmaxf(acc[r][c] + bao[col], 0.f);
        }
    }
}

// ============================================================
extern "C" void kernel_launch(void* const* d_in, const int* in_sizes, int n_in,
                              void* d_out, int out_size) {
    const float* atom = (const float*)d_in[0];
    const float* path = (const float*)d_in[1];
    const float* mask = (const float*)d_in[2];
    const float* Wai  = (const float*)d_in[3];
    const float* Wah  = (const float*)d_in[4];
    const float* bah  = (const float*)d_in[5];
    const float* Wo   = (const float*)d_in[6];
    const float* bo   = (const float*)d_in[7];
    const float* Wmh  = (const float*)d_in[8];
    const float* bmh  = (const float*)d_in[9];
    const float* Wao  = (const float*)d_in[10];
    const float* bao  = (const float*)d_in[11];
    float* out = (float*)d_out;

    const int SMEM_B = (128*FP + FP*160) * 4;    // 117,504 B
    const int SMEM_P = (128*DKK + DKK*160) * 4;  //  92,160 B
    cudaFuncSetAttribute(k_pathproj, cudaFuncAttributeMaxDynamicSharedMemorySize, SMEM_B);
    cudaFuncSetAttribute(k_proj4,    cudaFuncAttributeMaxDynamicSharedMemorySize, SMEM_P);

    k_proj0   <<<dim3(32, 8),  256>>>(atom, Wai);
    k_pathproj<<<1024,         256, SMEM_B>>>(path, Wah, Wmh, bah);
    k_proj4   <<<dim3(128, 2), 256, SMEM_P>>>(Wah, Wmh);     // layer 1 projections
    k_attn    <<<ROWS,         256>>>(mask, Wo, bo, bmh, 0); // layer 1 -> g_atomh
    k_proj4   <<<dim3(128, 2), 256, SMEM_P>>>(Wah, Wmh);     // layer 2 projections
    k_attn    <<<ROWS,         256>>>(mask, Wo, bo, bmh, 1); // layer 2 -> g_cat
    k_final   <<<dim3(32, 4),  256>>>(Wao, bao, out);
}

// round 9
// speedup vs baseline: 1.7235x; 1.7235x over previous
#include <cuda_runtime.h>

// ---------------- problem constants ----------------
#define BB      32
#define NN      64
#define FA      82
#define FP      102
#define HH      8
#define DKK     80
#define HID     256
#define HB      (HH*BB)        // 256
#define ROWS    (BB*NN)        // 2048
#define PAIRS   (BB*NN*NN)     // 131072
#define CATK    722
#define CATS    724            // padded row stride for concat matrix

// ---------------- device scratch (no allocations allowed) ----------------
__device__ float g_Pc[(size_t)PAIRS*DKK];     // compacted: (path@W1p)+b_attn_h, by global active slot t
__device__ float g_Qc[(size_t)PAIRS*DKK];     // compacted: path@W2p
__device__ float g_atom0[(size_t)HB*NN*DKK];  // atom_h0 [h*B+b, n, d]
__device__ float g_atomh[(size_t)HB*NN*DKK];  // current atom_h
__device__ float g_u [(size_t)HB*NN*DKK];     // atomh @ W1a
__device__ float g_v [(size_t)HB*NN*DKK];     // atomh @ W1b
__device__ float g_ws[(size_t)HB*NN*DKK];     // atomh @ W2a (self part of msg)
__device__ float g_w [(size_t)HB*NN*DKK];     // atomh @ W2b
__device__ float g_cat[(size_t)ROWS*CATS];    // [atom_input | merged heads]
__device__ int   g_cnt[ROWS];                 // active-j count per (b,i)
__device__ int   g_start[ROWS+1];             // exclusive prefix; g_start[ROWS] = total T
__device__ int   g_jidx[ROWS*NN];             // active j list per (b,i), fixed stride 64

// ============================================================
// Kernel M: per-(b,i) active-j list via warp ballot. 8 warps/CTA, warp = one row.
// ============================================================
__global__ void __launch_bounds__(256) k_mask(const float* __restrict__ mask) {
    const int bi = blockIdx.x * 8 + (threadIdx.x >> 5);
    const int lane = threadIdx.x & 31;
    const float m0 = mask[(size_t)bi*NN + lane];
    const float m1 = mask[(size_t)bi*NN + 32 + lane];
    const unsigned b0 = __ballot_sync(0xffffffffu, m0 != 0.f);
    const unsigned b1 = __ballot_sync(0xffffffffu, m1 != 0.f);
    const unsigned lt = (1u << lane) - 1u;
    const int c0 = __popc(b0);
    if (m0 != 0.f) g_jidx[bi*NN + __popc(b0 & lt)] = lane;
    if (m1 != 0.f) g_jidx[bi*NN + c0 + __popc(b1 & lt)] = lane + 32;
    if (lane == 0) g_cnt[bi] = c0 + __popc(b1);
}

// ============================================================
// Kernel S: exclusive prefix sum of g_cnt[2048] -> g_start. One CTA, 256 thr x 8.
// ============================================================
__global__ void __launch_bounds__(256) k_scan() {
    __shared__ int warp_sums[8];
    __shared__ int warp_off[8];
    const int tid = threadIdx.x;
    const int base = tid * 8;
    int v[8]; int tot = 0;
#pragma unroll
    for (int i = 0; i < 8; i++) { v[i] = g_cnt[base + i]; tot += v[i]; }
    const int lane = tid & 31, wid = tid >> 5;
    int x = tot;
#pragma unroll
    for (int o = 1; o < 32; o <<= 1) {
        int y = __shfl_up_sync(0xffffffffu, x, o);
        if (lane >= o) x += y;
    }
    if (lane == 31) warp_sums[wid] = x;
    __syncthreads();
    if (tid == 0) {
        int a = 0;
#pragma unroll
        for (int w = 0; w < 8; w++) { warp_off[w] = a; a += warp_sums[w]; }
        g_start[ROWS] = a;
    }
    __syncthreads();
    int a = x - tot + warp_off[wid];   // exclusive offset of this thread's chunk
#pragma unroll
    for (int i = 0; i < 8; i++) { g_start[base + i] = a; a += v[i]; }
}

// ============================================================
// Kernel A: atom_h0 = atom_input @ W_atom_i  (and init g_atomh, g_cat[:, :82])
// ============================================================
__global__ void __launch_bounds__(256) k_proj0(const float* __restrict__ atom,
                                               const float* __restrict__ Wai) {
    __shared__ float As[64*FA];
    __shared__ float Bs[FA*DKK];
    const int tid = threadIdx.x;
    const int r0 = blockIdx.x * 64;
    const int h  = blockIdx.y;
    const int c0 = h * DKK;

    for (int i = tid; i < 64*FA; i += 256) As[i] = atom[(size_t)r0*FA + i];
    for (int i = tid; i < FA*DKK; i += 256) {
        int k = i / DKK, c = i % DKK;
        Bs[i] = Wai[(size_t)k*(HH*DKK) + c0 + c];
    }
    __syncthreads();

    const int ty = tid >> 4, tx = tid & 15;
    float acc[4][5];
#pragma unroll
    for (int r = 0; r < 4; r++)
#pragma unroll
        for (int c = 0; c < 5; c++) acc[r][c] = 0.f;

    for (int k = 0; k < FA; k++) {
        float a[4], b[5];
#pragma unroll
        for (int r = 0; r < 4; r++) a[r] = As[(ty*4+r)*FA + k];
#pragma unroll
        for (int c = 0; c < 5; c++) b[c] = Bs[k*DKK + tx*5 + c];
#pragma unroll
        for (int r = 0; r < 4; r++)
#pragma unroll
            for (int c = 0; c < 5; c++) acc[r][c] += a[r]*b[c];
    }

#pragma unroll
    for (int r = 0; r < 4; r++) {
        int row = r0 + ty*4 + r;
#pragma unroll
        for (int c = 0; c < 5; c++) {
            int d = tx*5 + c;
            size_t o = ((size_t)h*ROWS + row)*DKK + d;
            g_atom0[o] = acc[r][c];
            g_atomh[o] = acc[r][c];
        }
    }
    if (blockIdx.y == 0) {
        for (int i = tid; i < 64*FA; i += 256)
            g_cat[(size_t)(r0 + i/FA)*CATS + (i % FA)] = As[i];
    }
}

// ============================================================
// Kernel B': masked path projection over compacted active pairs.
// Fixed grid 1024; CTAs beyond T exit. 128 global slots x 160 cols per CTA.
// ============================================================
__global__ void __launch_bounds__(256) k_pathprojm(const float* __restrict__ path,
                                                   const float* __restrict__ Wah,
                                                   const float* __restrict__ Wmh,
                                                   const float* __restrict__ bah) {
    const int T = g_start[ROWS];
    const int t0 = blockIdx.x * 128;
    if (t0 >= T) return;

    extern __shared__ float sm[];
    float* As = sm;               // [128][102]
    float* Bs = sm + 128*FP;      // [102][160]
    __shared__ int sPair[128];

    const int tid = threadIdx.x;

    // weight tile
    for (int i = tid; i < FP*160; i += 256) {
        int k = i / 160, c = i % 160;
        Bs[i] = (c < DKK) ? Wah[(size_t)(160+k)*DKK + c]
                          : Wmh[(size_t)(160+k)*DKK + (c - DKK)];
    }
    // map slots -> pair index (binary search in g_start)
    for (int s = tid; s < 128; s += 256) {
        int t = t0 + s; if (t >= T) t = T - 1;
        int lo = 0, hi = ROWS - 1;
        while (lo < hi) {
            int mid = (lo + hi + 1) >> 1;
            if (__ldg(&g_start[mid]) <= t) lo = mid; else hi = mid - 1;
        }
        int slot = t - __ldg(&g_start[lo]);
        sPair[s] = lo*NN + g_jidx[lo*NN + slot];
    }
    __syncthreads();

    // gather A rows (102 floats = 51 float2, 8-byte aligned since 102 is even)
    {
        const int row = tid >> 1, part = tid & 1;
        const float2* src = reinterpret_cast<const float2*>(path) + (size_t)sPair[row]*51;
        float2* dst = reinterpret_cast<float2*>(As) + (size_t)row*51;
        const int q0 = part ? 26 : 0, q1 = part ? 51 : 26;
        for (int q = q0; q < q1; q++) dst[q] = src[q];
    }
    __syncthreads();

    const int ty = tid >> 4, tx = tid & 15;   // 8 rows x 10 cols per thread
    float acc[8][10];
#pragma unroll
    for (int r = 0; r < 8; r++)
#pragma unroll
        for (int c = 0; c < 10; c++) acc[r][c] = 0.f;

    for (int k = 0; k < FP; k++) {
        float a[8], b[10];
#pragma unroll
        for (int r = 0; r < 8; r++) a[r] = As[(ty*8+r)*FP + k];
        const float2* bp = reinterpret_cast<const float2*>(Bs + k*160 + tx*10);
#pragma unroll
        for (int c = 0; c < 5; c++) { float2 t = bp[c]; b[2*c] = t.x; b[2*c+1] = t.y; }
#pragma unroll
        for (int r = 0; r < 8; r++)
#pragma unroll
            for (int c = 0; c < 10; c++) acc[r][c] += a[r]*b[c];
    }

#pragma unroll
    for (int r = 0; r < 8; r++) {
        int t = t0 + ty*8 + r;
        if (t >= T) continue;
#pragma unroll
        for (int c = 0; c < 10; c++) {
            int col = tx*10 + c;
            if (col < DKK) g_Pc[(size_t)t*DKK + col] = acc[r][c] + bah[col];
            else           g_Qc[(size_t)t*DKK + (col - DKK)] = acc[r][c];
        }
    }
}

// ============================================================
// Kernel P: {u, v, ws, w} = g_atomh[16384,80] @ [W1a|W1b|W2a|W2b][80,320]
// ============================================================
__global__ void __launch_bounds__(256) k_proj4(const float* __restrict__ Wah,
                                               const float* __restrict__ Wmh) {
    extern __shared__ float sm[];
    float* As = sm;               // [128][80]
    float* Bs = sm + 128*DKK;     // [80][160]
    const int tid = threadIdx.x;
    const size_t r0 = (size_t)blockIdx.x * 128;
    const int c0 = blockIdx.y * 160;

    {
        const float4* src = reinterpret_cast<const float4*>(g_atomh + r0*DKK);
        float4* dst = reinterpret_cast<float4*>(As);
        for (int i = tid; i < 128*DKK/4; i += 256) dst[i] = src[i];
    }
    for (int i = tid; i < DKK*160; i += 256) {
        int k = i / 160, c = i % 160;
        int cg = c0 + c;
        float v;
        if      (cg <  80) v = Wah[(size_t)k*DKK + cg];
        else if (cg < 160) v = Wah[(size_t)(80+k)*DKK + cg - 80];
        else if (cg < 240) v = Wmh[(size_t)k*DKK + cg - 160];
        else               v = Wmh[(size_t)(80+k)*DKK + cg - 240];
        Bs[i] = v;
    }
    __syncthreads();

    const int ty = tid >> 4, tx = tid & 15;
    float acc[8][10];
#pragma unroll
    for (int r = 0; r < 8; r++)
#pragma unroll
        for (int c = 0; c < 10; c++) acc[r][c] = 0.f;

    for (int k = 0; k < DKK; k++) {
        float a[8], b[10];
#pragma unroll
        for (int r = 0; r < 8; r++) a[r] = As[(ty*8+r)*DKK + k];
        const float2* bp = reinterpret_cast<const float2*>(Bs + k*160 + tx*10);
#pragma unroll
        for (int c = 0; c < 5; c++) { float2 t = bp[c]; b[2*c] = t.x; b[2*c+1] = t.y; }
#pragma unroll
        for (int r = 0; r < 8; r++)
#pragma unroll
            for (int c = 0; c < 10; c++) acc[r][c] += a[r]*b[c];
    }

#pragma unroll
    for (int r = 0; r < 8; r++) {
        size_t row = r0 + ty*8 + r;
#pragma unroll
        for (int c = 0; c < 10; c++) {
            int cg = c0 + tx*10 + c;
            float* dstp; int cc;
            if      (cg <  80) { dstp = g_u;  cc = cg;       }
            else if (cg < 160) { dstp = g_v;  cc = cg - 80;  }
            else if (cg < 240) { dstp = g_ws; cc = cg - 160; }
            else               { dstp = g_w;  cc = cg - 240; }
            dstp[row*DKK + cc] = acc[r][c];
        }
    }
}

// ============================================================
// Kernel C: message-passing layer over ACTIVE slots only. CTA=(b,i), warp=head.
// ============================================================
__global__ void __launch_bounds__(256) k_attn(const float* __restrict__ Wo,
                                              const float* __restrict__ bo,
                                              const float* __restrict__ bmsg,
                                              int mode) {
    __shared__ float sP[NN*DKK];
    __shared__ float sQ[NN*DKK];
    __shared__ float sSc[HH*NN];
    __shared__ float sPr[HH*NN];
    __shared__ int   sJ[NN];

    const int tid = threadIdx.x;
    const int bi = blockIdx.x;
    const int b = bi >> 6;
    const int cnt  = g_cnt[bi];
    const int base = g_start[bi];

    {   // compacted P/Q rows are contiguous: [base, base+cnt)
        const float4* ps = reinterpret_cast<const float4*>(g_Pc + (size_t)base*DKK);
        const float4* qs = reinterpret_cast<const float4*>(g_Qc + (size_t)base*DKK);
        float4* pd = reinterpret_cast<float4*>(sP);
        float4* qd = reinterpret_cast<float4*>(sQ);
        const int n4 = cnt * (DKK/4);
        for (int t = tid; t < n4; t += 256) { pd[t] = ps[t]; qd[t] = qs[t]; }
    }
    if (tid < cnt) sJ[tid] = g_jidx[bi*NN + tid];
    __syncthreads();

    const int h = tid >> 5, lane = tid & 31;
    const int hb = h*BB + b;
    const size_t base_i = ((size_t)hb*NN + (bi & 63))*DKK;

    const float* urow = g_u + base_i;
    const float u0 = urow[lane], u1 = urow[lane+32];
    const float u2 = (lane < 16) ? urow[64+lane] : 0.f;
    const float w0 = Wo[lane], w1 = Wo[lane+32];
    const float w2 = (lane < 16) ? Wo[64+lane] : 0.f;

    const float* V = g_v + (size_t)hb*NN*DKK;
    float* sc = sSc + h*NN;

    // ---- pass 1: scores over active slots ----
    for (int s = 0; s < cnt; s++) {
        const float* vr = V + (size_t)sJ[s]*DKK;
        float h0 = u0 + vr[lane]    + sP[s*DKK + lane];
        float h1 = u1 + vr[lane+32] + sP[s*DKK + 32 + lane];
        float h2 = 0.f;
        if (lane < 16) h2 = u2 + vr[64+lane] + sP[s*DKK + 64 + lane];
        h0 = h0 > 0.f ? h0 : 0.2f*h0;
        h1 = h1 > 0.f ? h1 : 0.2f*h1;
        h2 = h2 > 0.f ? h2 : 0.2f*h2;
        float sv = h0*w0 + h1*w1 + h2*w2;
        sv += __shfl_xor_sync(0xffffffffu, sv, 16);
        sv += __shfl_xor_sync(0xffffffffu, sv, 8);
        sv += __shfl_xor_sync(0xffffffffu, sv, 4);
        sv += __shfl_xor_sync(0xffffffffu, sv, 2);
        sv += __shfl_xor_sync(0xffffffffu, sv, 1);
        if (lane == 0) sc[s] = sv;
    }
    __syncwarp();

    // ---- masked softmax: active scores are (raw+bo); all masked scores are exactly 0 ----
    const float bov = bo[0];
    float s0 = (lane      < cnt) ? sc[lane]      + bov : -1e30f;
    float s1 = (lane + 32 < cnt) ? sc[lane + 32] + bov : -1e30f;
    float mx = fmaxf(s0, s1);
    mx = fmaxf(mx, __shfl_xor_sync(0xffffffffu, mx, 16));
    mx = fmaxf(mx, __shfl_xor_sync(0xffffffffu, mx, 8));
    mx = fmaxf(mx, __shfl_xor_sync(0xffffffffu, mx, 4));
    mx = fmaxf(mx, __shfl_xor_sync(0xffffffffu, mx, 2));
    mx = fmaxf(mx, __shfl_xor_sync(0xffffffffu, mx, 1));
    if (cnt < NN) mx = fmaxf(mx, 0.f);          // masked-out scores are exactly 0
    float e0 = (lane      < cnt) ? __expf(s0 - mx) : 0.f;
    float e1 = (lane + 32 < cnt) ? __expf(s1 - mx) : 0.f;
    float tot = e0 + e1;
    tot += __shfl_xor_sync(0xffffffffu, tot, 16);
    tot += __shfl_xor_sync(0xffffffffu, tot, 8);
    tot += __shfl_xor_sync(0xffffffffu, tot, 4);
    tot += __shfl_xor_sync(0xffffffffu, tot, 2);
    tot += __shfl_xor_sync(0xffffffffu, tot, 1);
    const float inv = 1.f / (tot + 1e-20f);
    sPr[h*NN + lane]      = e0 * inv;
    sPr[h*NN + lane + 32] = e1 * inv;
    const float S = tot * inv;                  // sum_j probs_j
    __syncwarp();

    // ---- pass 2: weighted message accumulation over active slots ----
    const float* W_ = g_w + (size_t)hb*NN*DKK;
    const float* pr = sPr + h*NN;
    float a0 = 0.f, a1 = 0.f, a2 = 0.f;
    for (int s = 0; s < cnt; s++) {
        const float p = pr[s];
        const float* wr = W_ + (size_t)sJ[s]*DKK;
        a0 += p * (wr[lane]    + sQ[s*DKK + lane]);
        a1 += p * (wr[lane+32] + sQ[s*DKK + 32 + lane]);
        if (lane < 16) a2 += p * (wr[64+lane] + sQ[s*DKK + 64 + lane]);
    }

    const float* wsr = g_ws   + base_i;
    const float* a0r = g_atom0 + base_i;
    float n0 = fmaxf(S*wsr[lane]    + a0 + bmsg[lane]    + a0r[lane],    0.f);
    float n1 = fmaxf(S*wsr[lane+32] + a1 + bmsg[lane+32] + a0r[lane+32], 0.f);
    float n2 = 0.f;
    if (lane < 16) n2 = fmaxf(S*wsr[64+lane] + a2 + bmsg[64+lane] + a0r[64+lane], 0.f);

    if (mode == 0) {
        float* o = g_atomh + base_i;
        o[lane] = n0; o[lane+32] = n1; if (lane < 16) o[64+lane] = n2;
    } else {
        float* o = g_cat + (size_t)bi*CATS + FA + h*DKK;
        o[lane] = n0; o[lane+32] = n1; if (lane < 16) o[64+lane] = n2;
    }
}

// ============================================================
// Kernel E: out = relu(g_cat[2048,722] @ W_atom_o[722,256] + b)
// ============================================================
__global__ void __launch_bounds__(256) k_final(const float* __restrict__ Wao,
                                               const float* __restrict__ bao,
                                               float* __restrict__ out) {
    __shared__ float As[64*64];
    __shared__ float Bs[64*64];
    const int tid = threadIdx.x;
    const int r0 = blockIdx.x * 64;
    const int c0 = blockIdx.y * 64;
    const int ty = tid >> 4, tx = tid & 15;

    float acc[4][4];
#pragma unroll
    for (int r = 0; r < 4; r++)
#pragma unroll
        for (int c = 0; c < 4; c++) acc[r][c] = 0.f;

    for (int k0 = 0; k0 < CATK; k0 += 64) {
        const int kc = (CATK - k0 < 64) ? (CATK - k0) : 64;
        for (int t = tid; t < 64*64; t += 256) {
            int r = t >> 6, k = t & 63;
            As[t] = (k < kc) ? g_cat[(size_t)(r0 + r)*CATS + k0 + k] : 0.f;
        }
        for (int t = tid; t < 64*64; t += 256) {
            int k = t >> 6, c = t & 63;
            Bs[t] = (k < kc) ? Wao[(size_t)(k0 + k)*HID + c0 + c] : 0.f;
        }
        __syncthreads();
#pragma unroll 8
        for (int k = 0; k < 64; k++) {
            float a[4], b[4];
#pragma unroll
            for (int r = 0; r < 4; r++) a[r] = As[(ty*4+r)*64 + k];
#pragma unroll
            for (int c = 0; c < 4; c++) b[c] = Bs[k*64 + tx*4 + c];
#pragma unroll
            for (int r = 0; r < 4; r++)
#pragma unroll
                for (int c = 0; c < 4; c++) acc[r][c] += a[r]*b[c];
        }
        __syncthreads();
    }

#pragma unroll
    for (int r = 0; r < 4; r++) {
        int row = r0 + ty*4 + r;
#pragma unroll
        for (int c = 0; c < 4; c++) {
            int col = c0 + tx*4 + c;
            out[(size_t)row*HID + col] = fmaxf(acc[r][c] + bao[col], 0.f);
        }
    }
}

// ============================================================
extern "C" void kernel_launch(void* const* d_in, const int* in_sizes, int n_in,
                              void* d_out, int out_size) {
    const float* atom = (const float*)d_in[0];
    const float* path = (const float*)d_in[1];
    const float* mask = (const float*)d_in[2];
    const float* Wai  = (const float*)d_in[3];
    const float* Wah  = (const float*)d_in[4];
    const float* bah  = (const float*)d_in[5];
    const float* Wo   = (const float*)d_in[6];
    const float* bo   = (const float*)d_in[7];
    const float* Wmh  = (const float*)d_in[8];
    const float* bmh  = (const float*)d_in[9];
    const float* Wao  = (const float*)d_in[10];
    const float* bao  = (const float*)d_in[11];
    float* out = (float*)d_out;

    const int SMEM_B = (128*FP + FP*160) * 4;    // 117,504 B
    const int SMEM_P = (128*DKK + DKK*160) * 4;  //  92,160 B
    cudaFuncSetAttribute(k_pathprojm, cudaFuncAttributeMaxDynamicSharedMemorySize, SMEM_B);
    cudaFuncSetAttribute(k_proj4,     cudaFuncAttributeMaxDynamicSharedMemorySize, SMEM_P);

    k_mask     <<<ROWS/8,       256>>>(mask);
    k_scan     <<<1,            256>>>();
    k_proj0    <<<dim3(32, 8),  256>>>(atom, Wai);
    k_pathprojm<<<1024,         256, SMEM_B>>>(path, Wah, Wmh, bah);
    k_proj4    <<<dim3(128, 2), 256, SMEM_P>>>(Wah, Wmh);    // layer 1 projections
    k_attn     <<<ROWS,         256>>>(Wo, bo, bmh, 0);      // layer 1 -> g_atomh
    k_proj4    <<<dim3(128, 2), 256, SMEM_P>>>(Wah, Wmh);    // layer 2 projections
    k_attn     <<<ROWS,         256>>>(Wo, bo, bmh, 1);      // layer 2 -> g_cat
    k_final    <<<dim3(32, 4),  256>>>(Wao, bao, out);
}

// round 10
// speedup vs baseline: 1.7337x; 1.0059x over previous
#include <cuda_runtime.h>

// ---------------- problem constants ----------------
#define BB      32
#define NN      64
#define FA      82
#define FP      102
#define HH      8
#define DKK     80
#define HID     256
#define HB      (HH*BB)        // 256
#define ROWS    (BB*NN)        // 2048
#define PAIRS   (BB*NN*NN)     // 131072
#define CATK    722
#define CATS    724            // padded row stride for concat matrix

// ---------------- device scratch (no allocations allowed) ----------------
__device__ float g_Pc[(size_t)PAIRS*DKK];     // compacted: (path@W1p)+b_attn_h, by global active slot t
__device__ float g_Qc[(size_t)PAIRS*DKK];     // compacted: path@W2p
__device__ float g_atom0[(size_t)HB*NN*DKK];  // atom_h0 [h*B+b, n, d]
__device__ float g_atomh[(size_t)HB*NN*DKK];  // current atom_h
__device__ float g_u [(size_t)HB*NN*DKK];     // atomh @ W1a
__device__ float g_v [(size_t)HB*NN*DKK];     // atomh @ W1b
__device__ float g_ws[(size_t)HB*NN*DKK];     // atomh @ W2a (self part of msg)
__device__ float g_w [(size_t)HB*NN*DKK];     // atomh @ W2b
__device__ float g_cat[(size_t)ROWS*CATS];    // [atom_input | merged heads]
__device__ int   g_cnt[ROWS];                 // active-j count per (b,i)
__device__ int   g_start[ROWS+1];             // exclusive prefix; g_start[ROWS] = total T
__device__ int   g_jidx[ROWS*NN];             // active j list per (b,i), fixed stride 64

// ============================================================
// Kernel M: per-(b,i) active-j list via warp ballot. 8 warps/CTA, warp = one row.
// ============================================================
__global__ void __launch_bounds__(256) k_mask(const float* __restrict__ mask) {
    const int bi = blockIdx.x * 8 + (threadIdx.x >> 5);
    const int lane = threadIdx.x & 31;
    const float m0 = mask[(size_t)bi*NN + lane];
    const float m1 = mask[(size_t)bi*NN + 32 + lane];
    const unsigned b0 = __ballot_sync(0xffffffffu, m0 != 0.f);
    const unsigned b1 = __ballot_sync(0xffffffffu, m1 != 0.f);
    const unsigned lt = (1u << lane) - 1u;
    const int c0 = __popc(b0);
    if (m0 != 0.f) g_jidx[bi*NN + __popc(b0 & lt)] = lane;
    if (m1 != 0.f) g_jidx[bi*NN + c0 + __popc(b1 & lt)] = lane + 32;
    if (lane == 0) g_cnt[bi] = c0 + __popc(b1);
}

// ============================================================
// Kernel S: exclusive prefix sum of g_cnt[2048] -> g_start. One CTA, 256 thr x 8.
// ============================================================
__global__ void __launch_bounds__(256) k_scan() {
    __shared__ int warp_sums[8];
    __shared__ int warp_off[8];
    const int tid = threadIdx.x;
    const int base = tid * 8;
    int v[8]; int tot = 0;
#pragma unroll
    for (int i = 0; i < 8; i++) { v[i] = g_cnt[base + i]; tot += v[i]; }
    const int lane = tid & 31, wid = tid >> 5;
    int x = tot;
#pragma unroll
    for (int o = 1; o < 32; o <<= 1) {
        int y = __shfl_up_sync(0xffffffffu, x, o);
        if (lane >= o) x += y;
    }
    if (lane == 31) warp_sums[wid] = x;
    __syncthreads();
    if (tid == 0) {
        int a = 0;
#pragma unroll
        for (int w = 0; w < 8; w++) { warp_off[w] = a; a += warp_sums[w]; }
        g_start[ROWS] = a;
    }
    __syncthreads();
    int a = x - tot + warp_off[wid];
#pragma unroll
    for (int i = 0; i < 8; i++) { g_start[base + i] = a; a += v[i]; }
}

// ============================================================
// Kernel A: atom_h0 = atom_input @ W_atom_i  (and init g_atomh, g_cat[:, :82])
// ============================================================
__global__ void __launch_bounds__(256) k_proj0(const float* __restrict__ atom,
                                               const float* __restrict__ Wai) {
    __shared__ float As[64*FA];
    __shared__ float Bs[FA*DKK];
    const int tid = threadIdx.x;
    const int r0 = blockIdx.x * 64;
    const int h  = blockIdx.y;
    const int c0 = h * DKK;

    for (int i = tid; i < 64*FA; i += 256) As[i] = atom[(size_t)r0*FA + i];
    for (int i = tid; i < FA*DKK; i += 256) {
        int k = i / DKK, c = i % DKK;
        Bs[i] = Wai[(size_t)k*(HH*DKK) + c0 + c];
    }
    __syncthreads();

    const int ty = tid >> 4, tx = tid & 15;
    float acc[4][5];
#pragma unroll
    for (int r = 0; r < 4; r++)
#pragma unroll
        for (int c = 0; c < 5; c++) acc[r][c] = 0.f;

    for (int k = 0; k < FA; k++) {
        float a[4], b[5];
#pragma unroll
        for (int r = 0; r < 4; r++) a[r] = As[(ty*4+r)*FA + k];
#pragma unroll
        for (int c = 0; c < 5; c++) b[c] = Bs[k*DKK + tx*5 + c];
#pragma unroll
        for (int r = 0; r < 4; r++)
#pragma unroll
            for (int c = 0; c < 5; c++) acc[r][c] += a[r]*b[c];
    }

#pragma unroll
    for (int r = 0; r < 4; r++) {
        int row = r0 + ty*4 + r;
#pragma unroll
        for (int c = 0; c < 5; c++) {
            int d = tx*5 + c;
            size_t o = ((size_t)h*ROWS + row)*DKK + d;
            g_atom0[o] = acc[r][c];
            g_atomh[o] = acc[r][c];
        }
    }
    if (blockIdx.y == 0) {
        for (int i = tid; i < 64*FA; i += 256)
            g_cat[(size_t)(r0 + i/FA)*CATS + (i % FA)] = As[i];
    }
}

// ============================================================
// Kernel B': masked path projection over compacted active pairs.
// Tile = 64 slots x 160 cols (smem 91KB -> 2 CTAs/SM). Grid 2048, early exit.
// ============================================================
__global__ void __launch_bounds__(256) k_pathprojm(const float* __restrict__ path,
                                                   const float* __restrict__ Wah,
                                                   const float* __restrict__ Wmh,
                                                   const float* __restrict__ bah) {
    const int T = g_start[ROWS];
    const int t0 = blockIdx.x * 64;
    if (t0 >= T) return;

    extern __shared__ float sm[];
    float* As = sm;               // [64][102]
    float* Bs = sm + 64*FP;       // [102][160]
    __shared__ int sPair[64];

    const int tid = threadIdx.x;

    // weight tile
    for (int i = tid; i < FP*160; i += 256) {
        int k = i / 160, c = i % 160;
        Bs[i] = (c < DKK) ? Wah[(size_t)(160+k)*DKK + c]
                          : Wmh[(size_t)(160+k)*DKK + (c - DKK)];
    }
    // map slots -> pair index (binary search in g_start)
    if (tid < 64) {
        int t = t0 + tid; if (t >= T) t = T - 1;
        int lo = 0, hi = ROWS - 1;
        while (lo < hi) {
            int mid = (lo + hi + 1) >> 1;
            if (__ldg(&g_start[mid]) <= t) lo = mid; else hi = mid - 1;
        }
        int slot = t - __ldg(&g_start[lo]);
        sPair[tid] = lo*NN + g_jidx[lo*NN + slot];
    }
    __syncthreads();

    // gather A rows: 4 threads per row, each ~13 float2 of 51
    {
        const int row = tid >> 2, part = tid & 3;
        const float2* src = reinterpret_cast<const float2*>(path) + (size_t)sPair[row]*51;
        float2* dst = reinterpret_cast<float2*>(As) + (size_t)row*51;
        const int q0 = part*13;
        const int q1 = (part == 3) ? 51 : q0 + 13;
        for (int q = q0; q < q1; q++) dst[q] = src[q];
    }
    __syncthreads();

    const int ty = tid >> 4, tx = tid & 15;   // 4 rows x 10 cols per thread
    float acc[4][10];
#pragma unroll
    for (int r = 0; r < 4; r++)
#pragma unroll
        for (int c = 0; c < 10; c++) acc[r][c] = 0.f;

    for (int k = 0; k < FP; k++) {
        float a[4], b[10];
#pragma unroll
        for (int r = 0; r < 4; r++) a[r] = As[(ty*4+r)*FP + k];
        const float2* bp = reinterpret_cast<const float2*>(Bs + k*160 + tx*10);
#pragma unroll
        for (int c = 0; c < 5; c++) { float2 t = bp[c]; b[2*c] = t.x; b[2*c+1] = t.y; }
#pragma unroll
        for (int r = 0; r < 4; r++)
#pragma unroll
            for (int c = 0; c < 10; c++) acc[r][c] += a[r]*b[c];
    }

#pragma unroll
    for (int r = 0; r < 4; r++) {
        int t = t0 + ty*4 + r;
        if (t >= T) continue;
#pragma unroll
        for (int c = 0; c < 10; c++) {
            int col = tx*10 + c;
            if (col < DKK) g_Pc[(size_t)t*DKK + col] = acc[r][c] + bah[col];
            else           g_Qc[(size_t)t*DKK + (col - DKK)] = acc[r][c];
        }
    }
}

// ============================================================
// Kernel P: {u, v, ws, w} = g_atomh[16384,80] @ [W1a|W1b|W2a|W2b][80,320]
// Tile = 64 rows x 160 cols (smem 71.7KB -> 3 CTAs/SM). Grid (256,2).
// ============================================================
__global__ void __launch_bounds__(256) k_proj4(const float* __restrict__ Wah,
                                               const float* __restrict__ Wmh) {
    extern __shared__ float sm[];
    float* As = sm;               // [64][80]
    float* Bs = sm + 64*DKK;      // [80][160]
    const int tid = threadIdx.x;
    const size_t r0 = (size_t)blockIdx.x * 64;
    const int c0 = blockIdx.y * 160;

    {
        const float4* src = reinterpret_cast<const float4*>(g_atomh + r0*DKK);
        float4* dst = reinterpret_cast<float4*>(As);
        for (int i = tid; i < 64*DKK/4; i += 256) dst[i] = src[i];
    }
    for (int i = tid; i < DKK*160; i += 256) {
        int k = i / 160, c = i % 160;
        int cg = c0 + c;
        float v;
        if      (cg <  80) v = Wah[(size_t)k*DKK + cg];
        else if (cg < 160) v = Wah[(size_t)(80+k)*DKK + cg - 80];
        else if (cg < 240) v = Wmh[(size_t)k*DKK + cg - 160];
        else               v = Wmh[(size_t)(80+k)*DKK + cg - 240];
        Bs[i] = v;
    }
    __syncthreads();

    const int ty = tid >> 4, tx = tid & 15;   // 4 rows x 10 cols per thread
    float acc[4][10];
#pragma unroll
    for (int r = 0; r < 4; r++)
#pragma unroll
        for (int c = 0; c < 10; c++) acc[r][c] = 0.f;

    for (int k = 0; k < DKK; k++) {
        float a[4], b[10];
#pragma unroll
        for (int r = 0; r < 4; r++) a[r] = As[(ty*4+r)*DKK + k];
        const float2* bp = reinterpret_cast<const float2*>(Bs + k*160 + tx*10);
#pragma unroll
        for (int c = 0; c < 5; c++) { float2 t = bp[c]; b[2*c] = t.x; b[2*c+1] = t.y; }
#pragma unroll
        for (int r = 0; r < 4; r++)
#pragma unroll
            for (int c = 0; c < 10; c++) acc[r][c] += a[r]*b[c];
    }

#pragma unroll
    for (int r = 0; r < 4; r++) {
        size_t row = r0 + ty*4 + r;
#pragma unroll
        for (int c = 0; c < 10; c++) {
            int cg = c0 + tx*10 + c;
            float* dstp; int cc;
            if      (cg <  80) { dstp = g_u;  cc = cg;       }
            else if (cg < 160) { dstp = g_v;  cc = cg - 80;  }
            else if (cg < 240) { dstp = g_ws; cc = cg - 160; }
            else               { dstp = g_w;  cc = cg - 240; }
            dstp[row*DKK + cc] = acc[r][c];
        }
    }
}

// ============================================================
// Kernel C: message-passing layer over ACTIVE slots only. CTA=(b,i), warp=head.
// ============================================================
__global__ void __launch_bounds__(256) k_attn(const float* __restrict__ Wo,
                                              const float* __restrict__ bo,
                                              const float* __restrict__ bmsg,
                                              int mode) {
    __shared__ float sP[NN*DKK];
    __shared__ float sQ[NN*DKK];
    __shared__ float sSc[HH*NN];
    __shared__ float sPr[HH*NN];
    __shared__ int   sJ[NN];

    const int tid = threadIdx.x;
    const int bi = blockIdx.x;
    const int b = bi >> 6;
    const int cnt  = g_cnt[bi];
    const int base = g_start[bi];

    {   // compacted P/Q rows are contiguous: [base, base+cnt)
        const float4* ps = reinterpret_cast<const float4*>(g_Pc + (size_t)base*DKK);
        const float4* qs = reinterpret_cast<const float4*>(g_Qc + (size_t)base*DKK);
        float4* pd = reinterpret_cast<float4*>(sP);
        float4* qd = reinterpret_cast<float4*>(sQ);
        const int n4 = cnt * (DKK/4);
        for (int t = tid; t < n4; t += 256) { pd[t] = ps[t]; qd[t] = qs[t]; }
    }
    if (tid < cnt) sJ[tid] = g_jidx[bi*NN + tid];
    __syncthreads();

    const int h = tid >> 5, lane = tid & 31;
    const int hb = h*BB + b;
    const size_t base_i = ((size_t)hb*NN + (bi & 63))*DKK;

    const float* urow = g_u + base_i;
    const float u0 = urow[lane], u1 = urow[lane+32];
    const float u2 = (lane < 16) ? urow[64+lane] : 0.f;
    const float w0 = Wo[lane], w1 = Wo[lane+32];
    const float w2 = (lane < 16) ? Wo[64+lane] : 0.f;

    const float* V = g_v + (size_t)hb*NN*DKK;
    float* sc = sSc + h*NN;

    // ---- pass 1: scores over active slots (x2 unrolled for MLP) ----
    int s = 0;
    for (; s + 1 < cnt; s += 2) {
        const float* vrA = V + (size_t)sJ[s]*DKK;
        const float* vrB = V + (size_t)sJ[s+1]*DKK;
        float A0 = vrA[lane], A1 = vrA[lane+32];
        float B0 = vrB[lane], B1 = vrB[lane+32];
        float A2 = 0.f, B2 = 0.f;
        if (lane < 16) { A2 = vrA[64+lane]; B2 = vrB[64+lane]; }
        float hA0 = u0 + A0 + sP[s*DKK + lane];
        float hA1 = u1 + A1 + sP[s*DKK + 32 + lane];
        float hA2 = (lane < 16) ? (u2 + A2 + sP[s*DKK + 64 + lane]) : 0.f;
        float hB0 = u0 + B0 + sP[(s+1)*DKK + lane];
        float hB1 = u1 + B1 + sP[(s+1)*DKK + 32 + lane];
        float hB2 = (lane < 16) ? (u2 + B2 + sP[(s+1)*DKK + 64 + lane]) : 0.f;
        hA0 = hA0 > 0.f ? hA0 : 0.2f*hA0;  hB0 = hB0 > 0.f ? hB0 : 0.2f*hB0;
        hA1 = hA1 > 0.f ? hA1 : 0.2f*hA1;  hB1 = hB1 > 0.f ? hB1 : 0.2f*hB1;
        hA2 = hA2 > 0.f ? hA2 : 0.2f*hA2;  hB2 = hB2 > 0.f ? hB2 : 0.2f*hB2;
        float sA = hA0*w0 + hA1*w1 + hA2*w2;
        float sB = hB0*w0 + hB1*w1 + hB2*w2;
#pragma unroll
        for (int o = 16; o >= 1; o >>= 1) {
            sA += __shfl_xor_sync(0xffffffffu, sA, o);
            sB += __shfl_xor_sync(0xffffffffu, sB, o);
        }
        if (lane == 0) { sc[s] = sA; sc[s+1] = sB; }
    }
    for (; s < cnt; s++) {
        const float* vr = V + (size_t)sJ[s]*DKK;
        float h0 = u0 + vr[lane]    + sP[s*DKK + lane];
        float h1 = u1 + vr[lane+32] + sP[s*DKK + 32 + lane];
        float h2 = 0.f;
        if (lane < 16) h2 = u2 + vr[64+lane] + sP[s*DKK + 64 + lane];
        h0 = h0 > 0.f ? h0 : 0.2f*h0;
        h1 = h1 > 0.f ? h1 : 0.2f*h1;
        h2 = h2 > 0.f ? h2 : 0.2f*h2;
        float sv = h0*w0 + h1*w1 + h2*w2;
#pragma unroll
        for (int o = 16; o >= 1; o >>= 1) sv += __shfl_xor_sync(0xffffffffu, sv, o);
        if (lane == 0) sc[s] = sv;
    }
    __syncwarp();

    // ---- masked softmax: active scores are (raw+bo); masked scores are exactly 0 ----
    const float bov = bo[0];
    float s0 = (lane      < cnt) ? sc[lane]      + bov : -1e30f;
    float s1 = (lane + 32 < cnt) ? sc[lane + 32] + bov : -1e30f;
    float mx = fmaxf(s0, s1);
#pragma unroll
    for (int o = 16; o >= 1; o >>= 1) mx = fmaxf(mx, __shfl_xor_sync(0xffffffffu, mx, o));
    if (cnt < NN) mx = fmaxf(mx, 0.f);
    float e0 = (lane      < cnt) ? __expf(s0 - mx) : 0.f;
    float e1 = (lane + 32 < cnt) ? __expf(s1 - mx) : 0.f;
    float tot = e0 + e1;
#pragma unroll
    for (int o = 16; o >= 1; o >>= 1) tot += __shfl_xor_sync(0xffffffffu, tot, o);
    const float inv = 1.f / (tot + 1e-20f);
    sPr[h*NN + lane]      = e0 * inv;
    sPr[h*NN + lane + 32] = e1 * inv;
    const float S = tot * inv;
    __syncwarp();

    // ---- pass 2: weighted message accumulation (x2 unrolled) ----
    const float* W_ = g_w + (size_t)hb*NN*DKK;
    const float* pr = sPr + h*NN;
    float a0 = 0.f, a1 = 0.f, a2 = 0.f;
    s = 0;
    for (; s + 1 < cnt; s += 2) {
        const float pA = pr[s], pB = pr[s+1];
        const float* wrA = W_ + (size_t)sJ[s]*DKK;
        const float* wrB = W_ + (size_t)sJ[s+1]*DKK;
        float A0 = wrA[lane], A1 = wrA[lane+32];
        float B0 = wrB[lane], B1 = wrB[lane+32];
        a0 += pA * (A0 + sQ[s*DKK + lane]);
        a1 += pA * (A1 + sQ[s*DKK + 32 + lane]);
        a0 += pB * (B0 + sQ[(s+1)*DKK + lane]);
        a1 += pB * (B1 + sQ[(s+1)*DKK + 32 + lane]);
        if (lane < 16) {
            a2 += pA * (wrA[64+lane] + sQ[s*DKK + 64 + lane]);
            a2 += pB * (wrB[64+lane] + sQ[(s+1)*DKK + 64 + lane]);
        }
    }
    for (; s < cnt; s++) {
        const float p = pr[s];
        const float* wr = W_ + (size_t)sJ[s]*DKK;
        a0 += p * (wr[lane]    + sQ[s*DKK + lane]);
        a1 += p * (wr[lane+32] + sQ[s*DKK + 32 + lane]);
        if (lane < 16) a2 += p * (wr[64+lane] + sQ[s*DKK + 64 + lane]);
    }

    const float* wsr = g_ws   + base_i;
    const float* a0r = g_atom0 + base_i;
    float n0 = fmaxf(S*wsr[lane]    + a0 + bmsg[lane]    + a0r[lane],    0.f);
    float n1 = fmaxf(S*wsr[lane+32] + a1 + bmsg[lane+32] + a0r[lane+32], 0.f);
    float n2 = 0.f;
    if (lane < 16) n2 = fmaxf(S*wsr[64+lane] + a2 + bmsg[64+lane] + a0r[64+lane], 0.f);

    if (mode == 0) {
        float* o = g_atomh + base_i;
        o[lane] = n0; o[lane+32] = n1; if (lane < 16) o[64+lane] = n2;
    } else {
        float* o = g_cat + (size_t)bi*CATS + FA + h*DKK;
        o[lane] = n0; o[lane+32] = n1; if (lane < 16) o[64+lane] = n2;
    }
}

// ============================================================
// Kernel E: out = relu(g_cat[2048,722] @ W_atom_o[722,256] + b)
// ============================================================
__global__ void __launch_bounds__(256) k_final(const float* __restrict__ Wao,
                                               const float* __restrict__ bao,
                                               float* __restrict__ out) {
    __shared__ float As[64*64];
    __shared__ float Bs[64*64];
    const int tid = threadIdx.x;
    const int r0 = blockIdx.x * 64;
    const int c0 = blockIdx.y * 64;
    const int ty = tid >> 4, tx = tid & 15;

    float acc[4][4];
#pragma unroll
    for (int r = 0; r < 4; r++)
#pragma unroll
        for (int c = 0; c < 4; c++) acc[r][c] = 0.f;

    for (int k0 = 0; k0 < CATK; k0 += 64) {
        const int kc = (CATK - k0 < 64) ? (CATK - k0) : 64;
        for (int t = tid; t < 64*64; t += 256) {
            int r = t >> 6, k = t & 63;
            As[t] = (k < kc) ? g_cat[(size_t)(r0 + r)*CATS + k0 + k] : 0.f;
        }
        for (int t = tid; t < 64*64; t += 256) {
            int k = t >> 6, c = t & 63;
            Bs[t] = (k < kc) ? Wao[(size_t)(k0 + k)*HID + c0 + c] : 0.f;
        }
        __syncthreads();
#pragma unroll 8
        for (int k = 0; k < 64; k++) {
            float a[4];
#pragma unroll
            for (int r = 0; r < 4; r++) a[r] = As[(ty*4+r)*64 + k];
            const float4 bv = *reinterpret_cast<const float4*>(Bs + k*64 + tx*4);
            const float b[4] = {bv.x, bv.y, bv.z, bv.w};
#pragma unroll
            for (int r = 0; r < 4; r++)
#pragma unroll
                for (int c = 0; c < 4; c++) acc[r][c] += a[r]*b[c];
        }
        __syncthreads();
    }

#pragma unroll
    for (int r = 0; r < 4; r++) {
        int row = r0 + ty*4 + r;
#pragma unroll
        for (int c = 0; c < 4; c++) {
            int col = c0 + tx*4 + c;
            out[(size_t)row*HID + col] = fmaxf(acc[r][c] + bao[col], 0.f);
        }
    }
}

// ============================================================
extern "C" void kernel_launch(void* const* d_in, const int* in_sizes, int n_in,
                              void* d_out, int out_size) {
    const float* atom = (const float*)d_in[0];
    const float* path = (const float*)d_in[1];
    const float* mask = (const float*)d_in[2];
    const float* Wai  = (const float*)d_in[3];
    const float* Wah  = (const float*)d_in[4];
    const float* bah  = (const float*)d_in[5];
    const float* Wo   = (const float*)d_in[6];
    const float* bo   = (const float*)d_in[7];
    const float* Wmh  = (const float*)d_in[8];
    const float* bmh  = (const float*)d_in[9];
    const float* Wao  = (const float*)d_in[10];
    const float* bao  = (const float*)d_in[11];
    float* out = (float*)d_out;

    const int SMEM_B = (64*FP + FP*160) * 4;     //  91,392 B -> 2 CTAs/SM
    const int SMEM_P = (64*DKK + DKK*160) * 4;   //  71,680 B -> 3 CTAs/SM
    cudaFuncSetAttribute(k_pathprojm, cudaFuncAttributeMaxDynamicSharedMemorySize, SMEM_B);
    cudaFuncSetAttribute(k_proj4,     cudaFuncAttributeMaxDynamicSharedMemorySize, SMEM_P);

    k_mask     <<<ROWS/8,       256>>>(mask);
    k_scan     <<<1,            256>>>();
    k_proj0    <<<dim3(32, 8),  256>>>(atom, Wai);
    k_pathprojm<<<PAIRS/64,     256, SMEM_B>>>(path, Wah, Wmh, bah);
    k_proj4    <<<dim3(256, 2), 256, SMEM_P>>>(Wah, Wmh);    // layer 1 projections
    k_attn     <<<ROWS,         256>>>(Wo, bo, bmh, 0);      // layer 1 -> g_atomh
    k_proj4    <<<dim3(256, 2), 256, SMEM_P>>>(Wah, Wmh);    // layer 2 projections
    k_attn     <<<ROWS,         256>>>(Wo, bo, bmh, 1);      // layer 2 -> g_cat
    k_final    <<<dim3(32, 4),  256>>>(Wao, bao, out);
}

// round 11
// speedup vs baseline: 1.8112x; 1.0447x over previous
#include <cuda_runtime.h>

// ---------------- problem constants ----------------
#define BB      32
#define NN      64
#define FA      82
#define FP      102
#define HH      8
#define DKK     80
#define HID     256
#define HB      (HH*BB)        // 256
#define ROWS    (BB*NN)        // 2048
#define PAIRS   (BB*NN*NN)     // 131072
#define CATK    722
#define CATS    724            // padded row stride for concat matrix
#define TPAD    68             // transposed-A smem row stride (16B multiple)

// ---------------- f32x2 packed helpers (sm_103a FFMA2) ----------------
__device__ __forceinline__ unsigned long long pk2(float x) {
    unsigned long long d;
    asm("mov.b64 %0, {%1, %1};" : "=l"(d) : "r"(__float_as_uint(x)));
    return d;
}
__device__ __forceinline__ unsigned long long ffma2(unsigned long long a,
                                                    unsigned long long b,
                                                    unsigned long long c) {
    unsigned long long d;
    asm("fma.rn.f32x2 %0, %1, %2, %3;" : "=l"(d) : "l"(a), "l"(b), "l"(c));
    return d;
}
__device__ __forceinline__ float2 upk2(unsigned long long d) {
    unsigned lo, hi;
    asm("mov.b64 {%0, %1}, %2;" : "=r"(lo), "=r"(hi) : "l"(d));
    return make_float2(__uint_as_float(lo), __uint_as_float(hi));
}

// ---------------- device scratch (no allocations allowed) ----------------
__device__ float g_Pc[(size_t)PAIRS*DKK];     // compacted: (path@W1p)+b_attn_h
__device__ float g_Qc[(size_t)PAIRS*DKK];     // compacted: path@W2p
__device__ float g_atom0[(size_t)HB*NN*DKK];  // atom_h0 [h*B+b, n, d]
__device__ float g_atomh[(size_t)HB*NN*DKK];  // current atom_h
__device__ float g_u [(size_t)HB*NN*DKK];
__device__ float g_v [(size_t)HB*NN*DKK];
__device__ float g_ws[(size_t)HB*NN*DKK];
__device__ float g_w [(size_t)HB*NN*DKK];
__device__ float g_cat[(size_t)ROWS*CATS];    // [atom_input | merged heads]
__device__ int   g_cnt[ROWS];
__device__ int   g_start[ROWS+1];
__device__ int   g_jidx[ROWS*NN];

// ============================================================
// Kernel M: per-(b,i) active-j list via warp ballot.
// ============================================================
__global__ void __launch_bounds__(256) k_mask(const float* __restrict__ mask) {
    const int bi = blockIdx.x * 8 + (threadIdx.x >> 5);
    const int lane = threadIdx.x & 31;
    const float m0 = mask[(size_t)bi*NN + lane];
    const float m1 = mask[(size_t)bi*NN + 32 + lane];
    const unsigned b0 = __ballot_sync(0xffffffffu, m0 != 0.f);
    const unsigned b1 = __ballot_sync(0xffffffffu, m1 != 0.f);
    const unsigned lt = (1u << lane) - 1u;
    const int c0 = __popc(b0);
    if (m0 != 0.f) g_jidx[bi*NN + __popc(b0 & lt)] = lane;
    if (m1 != 0.f) g_jidx[bi*NN + c0 + __popc(b1 & lt)] = lane + 32;
    if (lane == 0) g_cnt[bi] = c0 + __popc(b1);
}

// ============================================================
// Kernel S: exclusive prefix sum of g_cnt[2048] -> g_start. One CTA.
// ============================================================
__global__ void __launch_bounds__(256) k_scan() {
    __shared__ int warp_sums[8];
    __shared__ int warp_off[8];
    const int tid = threadIdx.x;
    const int base = tid * 8;
    int v[8]; int tot = 0;
#pragma unroll
    for (int i = 0; i < 8; i++) { v[i] = g_cnt[base + i]; tot += v[i]; }
    const int lane = tid & 31, wid = tid >> 5;
    int x = tot;
#pragma unroll
    for (int o = 1; o < 32; o <<= 1) {
        int y = __shfl_up_sync(0xffffffffu, x, o);
        if (lane >= o) x += y;
    }
    if (lane == 31) warp_sums[wid] = x;
    __syncthreads();
    if (tid == 0) {
        int a = 0;
#pragma unroll
        for (int w = 0; w < 8; w++) { warp_off[w] = a; a += warp_sums[w]; }
        g_start[ROWS] = a;
    }
    __syncthreads();
    int a = x - tot + warp_off[wid];
#pragma unroll
    for (int i = 0; i < 8; i++) { g_start[base + i] = a; a += v[i]; }
}

// ============================================================
// Kernel A: atom_h0 = atom_input @ W_atom_i (init g_atomh, g_cat[:, :82])
// ============================================================
__global__ void __launch_bounds__(256) k_proj0(const float* __restrict__ atom,
                                               const float* __restrict__ Wai) {
    __shared__ float As[64*FA];
    __shared__ float Bs[FA*DKK];
    const int tid = threadIdx.x;
    const int r0 = blockIdx.x * 64;
    const int h  = blockIdx.y;
    const int c0 = h * DKK;

    for (int i = tid; i < 64*FA; i += 256) As[i] = atom[(size_t)r0*FA + i];
    for (int i = tid; i < FA*DKK; i += 256) {
        int k = i / DKK, c = i % DKK;
        Bs[i] = Wai[(size_t)k*(HH*DKK) + c0 + c];
    }
    __syncthreads();

    const int ty = tid >> 4, tx = tid & 15;
    float acc[4][5];
#pragma unroll
    for (int r = 0; r < 4; r++)
#pragma unroll
        for (int c = 0; c < 5; c++) acc[r][c] = 0.f;

    for (int k = 0; k < FA; k++) {
        float a[4], b[5];
#pragma unroll
        for (int r = 0; r < 4; r++) a[r] = As[(ty*4+r)*FA + k];
#pragma unroll
        for (int c = 0; c < 5; c++) b[c] = Bs[k*DKK + tx*5 + c];
#pragma unroll
        for (int r = 0; r < 4; r++)
#pragma unroll
            for (int c = 0; c < 5; c++) acc[r][c] += a[r]*b[c];
    }

#pragma unroll
    for (int r = 0; r < 4; r++) {
        int row = r0 + ty*4 + r;
#pragma unroll
        for (int c = 0; c < 5; c++) {
            int d = tx*5 + c;
            size_t o = ((size_t)h*ROWS + row)*DKK + d;
            g_atom0[o] = acc[r][c];
            g_atomh[o] = acc[r][c];
        }
    }
    if (blockIdx.y == 0) {
        for (int i = tid; i < 64*FA; i += 256)
            g_cat[(size_t)(r0 + i/FA)*CATS + (i % FA)] = As[i];
    }
}

// ============================================================
// Kernel B': masked path projection, transposed-A smem + FFMA2.
// Tile = 64 slots x 160 cols. Grid 2048, early exit.
// ============================================================
__global__ void __launch_bounds__(256) k_pathprojm(const float* __restrict__ path,
                                                   const float* __restrict__ Wah,
                                                   const float* __restrict__ Wmh,
                                                   const float* __restrict__ bah) {
    const int T = g_start[ROWS];
    const int t0 = blockIdx.x * 64;
    if (t0 >= T) return;

    extern __shared__ float sm[];
    float* At = sm;               // [FP][TPAD] transposed A
    float* Bs = sm + FP*TPAD;     // [FP][160]
    __shared__ int sPair[64];

    const int tid = threadIdx.x;

    for (int i = tid; i < FP*160; i += 256) {
        int k = i / 160, c = i % 160;
        Bs[i] = (c < DKK) ? Wah[(size_t)(160+k)*DKK + c]
                          : Wmh[(size_t)(160+k)*DKK + (c - DKK)];
    }
    if (tid < 64) {
        int t = t0 + tid; if (t >= T) t = T - 1;
        int lo = 0, hi = ROWS - 1;
        while (lo < hi) {
            int mid = (lo + hi + 1) >> 1;
            if (__ldg(&g_start[mid]) <= t) lo = mid; else hi = mid - 1;
        }
        int slot = t - __ldg(&g_start[lo]);
        sPair[tid] = lo*NN + g_jidx[lo*NN + slot];
    }
    __syncthreads();

    // gather A rows transposed: 4 threads per row, scalar scatter into At[k][row]
    {
        const int row = tid >> 2, part = tid & 3;
        const float2* src = reinterpret_cast<const float2*>(path) + (size_t)sPair[row]*51;
        const int q0 = part*13;
        const int q1 = (part == 3) ? 51 : q0 + 13;
        for (int q = q0; q < q1; q++) {
            float2 v = src[q];
            At[(2*q)  *TPAD + row] = v.x;
            At[(2*q+1)*TPAD + row] = v.y;
        }
    }
    __syncthreads();

    const int ty = tid >> 4, tx = tid & 15;   // 4 rows x 10 cols per thread
    unsigned long long acc[4][5];
#pragma unroll
    for (int r = 0; r < 4; r++)
#pragma unroll
        for (int c = 0; c < 5; c++) acc[r][c] = 0ull;

#pragma unroll 2
    for (int k = 0; k < FP; k++) {
        const float4 av = *reinterpret_cast<const float4*>(At + k*TPAD + ty*4);
        const unsigned long long a0 = pk2(av.x), a1 = pk2(av.y),
                                 a2 = pk2(av.z), a3 = pk2(av.w);
        const unsigned long long* bp =
            reinterpret_cast<const unsigned long long*>(Bs + k*160 + tx*10);
        unsigned long long b[5];
#pragma unroll
        for (int c = 0; c < 5; c++) b[c] = bp[c];
#pragma unroll
        for (int c = 0; c < 5; c++) {
            acc[0][c] = ffma2(a0, b[c], acc[0][c]);
            acc[1][c] = ffma2(a1, b[c], acc[1][c]);
            acc[2][c] = ffma2(a2, b[c], acc[2][c]);
            acc[3][c] = ffma2(a3, b[c], acc[3][c]);
        }
    }

#pragma unroll
    for (int r = 0; r < 4; r++) {
        int t = t0 + ty*4 + r;
        if (t >= T) continue;
#pragma unroll
        for (int c = 0; c < 5; c++) {
            const int col = tx*10 + 2*c;       // chunk never straddles col 80
            const float2 v = upk2(acc[r][c]);
            if (col < DKK) {
                g_Pc[(size_t)t*DKK + col]     = v.x + bah[col];
                g_Pc[(size_t)t*DKK + col + 1] = v.y + bah[col + 1];
            } else {
                g_Qc[(size_t)t*DKK + (col - DKK)]     = v.x;
                g_Qc[(size_t)t*DKK + (col - DKK) + 1] = v.y;
            }
        }
    }
}

// ============================================================
// Kernel P: {u,v,ws,w} = g_atomh @ [W1a|W1b|W2a|W2b], transposed-A + FFMA2.
// Tile = 64 rows x 160 cols. Grid (256, 2). smem 73KB -> 3 CTAs/SM.
// ============================================================
__global__ void __launch_bounds__(256) k_proj4(const float* __restrict__ Wah,
                                               const float* __restrict__ Wmh) {
    extern __shared__ float sm[];
    float* At = sm;               // [DKK][TPAD] transposed A
    float* Bs = sm + DKK*TPAD;    // [DKK][160]
    const int tid = threadIdx.x;
    const size_t r0 = (size_t)blockIdx.x * 64;
    const int c0 = blockIdx.y * 160;

    {   // gather transposed: 4 threads per row, 10 float2 each
        const int row = tid >> 2, part = tid & 3;
        const float2* src = reinterpret_cast<const float2*>(g_atomh + (r0 + row)*DKK);
        const int q0 = part*10;
#pragma unroll
        for (int q = q0; q < q0 + 10; q++) {
            float2 v = src[q];
            At[(2*q)  *TPAD + row] = v.x;
            At[(2*q+1)*TPAD + row] = v.y;
        }
    }
    for (int i = tid; i < DKK*160; i += 256) {
        int k = i / 160, c = i % 160;
        int cg = c0 + c;
        float v;
        if      (cg <  80) v = Wah[(size_t)k*DKK + cg];
        else if (cg < 160) v = Wah[(size_t)(80+k)*DKK + cg - 80];
        else if (cg < 240) v = Wmh[(size_t)k*DKK + cg - 160];
        else               v = Wmh[(size_t)(80+k)*DKK + cg - 240];
        Bs[i] = v;
    }
    __syncthreads();

    const int ty = tid >> 4, tx = tid & 15;   // 4 rows x 10 cols per thread
    unsigned long long acc[4][5];
#pragma unroll
    for (int r = 0; r < 4; r++)
#pragma unroll
        for (int c = 0; c < 5; c++) acc[r][c] = 0ull;

#pragma unroll 2
    for (int k = 0; k < DKK; k++) {
        const float4 av = *reinterpret_cast<const float4*>(At + k*TPAD + ty*4);
        const unsigned long long a0 = pk2(av.x), a1 = pk2(av.y),
                                 a2 = pk2(av.z), a3 = pk2(av.w);
        const unsigned long long* bp =
            reinterpret_cast<const unsigned long long*>(Bs + k*160 + tx*10);
        unsigned long long b[5];
#pragma unroll
        for (int c = 0; c < 5; c++) b[c] = bp[c];
#pragma unroll
        for (int c = 0; c < 5; c++) {
            acc[0][c] = ffma2(a0, b[c], acc[0][c]);
            acc[1][c] = ffma2(a1, b[c], acc[1][c]);
            acc[2][c] = ffma2(a2, b[c], acc[2][c]);
            acc[3][c] = ffma2(a3, b[c], acc[3][c]);
        }
    }

#pragma unroll
    for (int r = 0; r < 4; r++) {
        size_t row = r0 + ty*4 + r;
#pragma unroll
        for (int c = 0; c < 5; c++) {
            int cg = c0 + tx*10 + 2*c;         // chunk never straddles an 80-block
            const float2 v = upk2(acc[r][c]);
            float* dstp; int cc;
            if      (cg <  80) { dstp = g_u;  cc = cg;       }
            else if (cg < 160) { dstp = g_v;  cc = cg - 80;  }
            else if (cg < 240) { dstp = g_ws; cc = cg - 160; }
            else               { dstp = g_w;  cc = cg - 240; }
            dstp[row*DKK + cc]     = v.x;
            dstp[row*DKK + cc + 1] = v.y;
        }
    }
}

// ============================================================
// Kernel C: message-passing layer over ACTIVE slots only. CTA=(b,i), warp=head.
// ============================================================
__global__ void __launch_bounds__(256) k_attn(const float* __restrict__ Wo,
                                              const float* __restrict__ bo,
                                              const float* __restrict__ bmsg,
                                              int mode) {
    __shared__ float sP[NN*DKK];
    __shared__ float sQ[NN*DKK];
    __shared__ float sSc[HH*NN];
    __shared__ float sPr[HH*NN];
    __shared__ int   sJ[NN];

    const int tid = threadIdx.x;
    const int bi = blockIdx.x;
    const int b = bi >> 6;
    const int cnt  = g_cnt[bi];
    const int base = g_start[bi];

    {
        const float4* ps = reinterpret_cast<const float4*>(g_Pc + (size_t)base*DKK);
        const float4* qs = reinterpret_cast<const float4*>(g_Qc + (size_t)base*DKK);
        float4* pd = reinterpret_cast<float4*>(sP);
        float4* qd = reinterpret_cast<float4*>(sQ);
        const int n4 = cnt * (DKK/4);
        for (int t = tid; t < n4; t += 256) { pd[t] = ps[t]; qd[t] = qs[t]; }
    }
    if (tid < cnt) sJ[tid] = g_jidx[bi*NN + tid];
    __syncthreads();

    const int h = tid >> 5, lane = tid & 31;
    const int hb = h*BB + b;
    const size_t base_i = ((size_t)hb*NN + (bi & 63))*DKK;

    const float* urow = g_u + base_i;
    const float u0 = urow[lane], u1 = urow[lane+32];
    const float u2 = (lane < 16) ? urow[64+lane] : 0.f;
    const float w0 = Wo[lane], w1 = Wo[lane+32];
    const float w2 = (lane < 16) ? Wo[64+lane] : 0.f;

    const float* V = g_v + (size_t)hb*NN*DKK;
    float* sc = sSc + h*NN;

    int s = 0;
    for (; s + 1 < cnt; s += 2) {
        const float* vrA = V + (size_t)sJ[s]*DKK;
        const float* vrB = V + (size_t)sJ[s+1]*DKK;
        float A0 = vrA[lane], A1 = vrA[lane+32];
        float B0 = vrB[lane], B1 = vrB[lane+32];
        float A2 = 0.f, B2 = 0.f;
        if (lane < 16) { A2 = vrA[64+lane]; B2 = vrB[64+lane]; }
        float hA0 = u0 + A0 + sP[s*DKK + lane];
        float hA1 = u1 + A1 + sP[s*DKK + 32 + lane];
        float hA2 = (lane < 16) ? (u2 + A2 + sP[s*DKK + 64 + lane]) : 0.f;
        float hB0 = u0 + B0 + sP[(s+1)*DKK + lane];
        float hB1 = u1 + B1 + sP[(s+1)*DKK + 32 + lane];
        float hB2 = (lane < 16) ? (u2 + B2 + sP[(s+1)*DKK + 64 + lane]) : 0.f;
        hA0 = hA0 > 0.f ? hA0 : 0.2f*hA0;  hB0 = hB0 > 0.f ? hB0 : 0.2f*hB0;
        hA1 = hA1 > 0.f ? hA1 : 0.2f*hA1;  hB1 = hB1 > 0.f ? hB1 : 0.2f*hB1;
        hA2 = hA2 > 0.f ? hA2 : 0.2f*hA2;  hB2 = hB2 > 0.f ? hB2 : 0.2f*hB2;
        float sA = hA0*w0 + hA1*w1 + hA2*w2;
        float sB = hB0*w0 + hB1*w1 + hB2*w2;
#pragma unroll
        for (int o = 16; o >= 1; o >>= 1) {
            sA += __shfl_xor_sync(0xffffffffu, sA, o);
            sB += __shfl_xor_sync(0xffffffffu, sB, o);
        }
        if (lane == 0) { sc[s] = sA; sc[s+1] = sB; }
    }
    for (; s < cnt; s++) {
        const float* vr = V + (size_t)sJ[s]*DKK;
        float h0 = u0 + vr[lane]    + sP[s*DKK + lane];
        float h1 = u1 + vr[lane+32] + sP[s*DKK + 32 + lane];
        float h2 = 0.f;
        if (lane < 16) h2 = u2 + vr[64+lane] + sP[s*DKK + 64 + lane];
        h0 = h0 > 0.f ? h0 : 0.2f*h0;
        h1 = h1 > 0.f ? h1 : 0.2f*h1;
        h2 = h2 > 0.f ? h2 : 0.2f*h2;
        float sv = h0*w0 + h1*w1 + h2*w2;
#pragma unroll
        for (int o = 16; o >= 1; o >>= 1) sv += __shfl_xor_sync(0xffffffffu, sv, o);
        if (lane == 0) sc[s] = sv;
    }
    __syncwarp();

    const float bov = bo[0];
    float s0 = (lane      < cnt) ? sc[lane]      + bov : -1e30f;
    float s1 = (lane + 32 < cnt) ? sc[lane + 32] + bov : -1e30f;
    float mx = fmaxf(s0, s1);
#pragma unroll
    for (int o = 16; o >= 1; o >>= 1) mx = fmaxf(mx, __shfl_xor_sync(0xffffffffu, mx, o));
    if (cnt < NN) mx = fmaxf(mx, 0.f);
    float e0 = (lane      < cnt) ? __expf(s0 - mx) : 0.f;
    float e1 = (lane + 32 < cnt) ? __expf(s1 - mx) : 0.f;
    float tot = e0 + e1;
#pragma unroll
    for (int o = 16; o >= 1; o >>= 1) tot += __shfl_xor_sync(0xffffffffu, tot, o);
    const float inv = 1.f / (tot + 1e-20f);
    sPr[h*NN + lane]      = e0 * inv;
    sPr[h*NN + lane + 32] = e1 * inv;
    const float S = tot * inv;
    __syncwarp();

    const float* W_ = g_w + (size_t)hb*NN*DKK;
    const float* pr = sPr + h*NN;
    float a0 = 0.f, a1 = 0.f, a2 = 0.f;
    s = 0;
    for (; s + 1 < cnt; s += 2) {
        const float pA = pr[s], pB = pr[s+1];
        const float* wrA = W_ + (size_t)sJ[s]*DKK;
        const float* wrB = W_ + (size_t)sJ[s+1]*DKK;
        float A0 = wrA[lane], A1 = wrA[lane+32];
        float B0 = wrB[lane], B1 = wrB[lane+32];
        a0 += pA * (A0 + sQ[s*DKK + lane]);
        a1 += pA * (A1 + sQ[s*DKK + 32 + lane]);
        a0 += pB * (B0 + sQ[(s+1)*DKK + lane]);
        a1 += pB * (B1 + sQ[(s+1)*DKK + 32 + lane]);
        if (lane < 16) {
            a2 += pA * (wrA[64+lane] + sQ[s*DKK + 64 + lane]);
            a2 += pB * (wrB[64+lane] + sQ[(s+1)*DKK + 64 + lane]);
        }
    }
    for (; s < cnt; s++) {
        const float p = pr[s];
        const float* wr = W_ + (size_t)sJ[s]*DKK;
        a0 += p * (wr[lane]    + sQ[s*DKK + lane]);
        a1 += p * (wr[lane+32] + sQ[s*DKK + 32 + lane]);
        if (lane < 16) a2 += p * (wr[64+lane] + sQ[s*DKK + 64 + lane]);
    }

    const float* wsr = g_ws   + base_i;
    const float* a0r = g_atom0 + base_i;
    float n0 = fmaxf(S*wsr[lane]    + a0 + bmsg[lane]    + a0r[lane],    0.f);
    float n1 = fmaxf(S*wsr[lane+32] + a1 + bmsg[lane+32] + a0r[lane+32], 0.f);
    float n2 = 0.f;
    if (lane < 16) n2 = fmaxf(S*wsr[64+lane] + a2 + bmsg[64+lane] + a0r[64+lane], 0.f);

    if (mode == 0) {
        float* o = g_atomh + base_i;
        o[lane] = n0; o[lane+32] = n1; if (lane < 16) o[64+lane] = n2;
    } else {
        float* o = g_cat + (size_t)bi*CATS + FA + h*DKK;
        o[lane] = n0; o[lane+32] = n1; if (lane < 16) o[64+lane] = n2;
    }
}

// ============================================================
// Kernel E: out = relu(g_cat[2048,722] @ W_atom_o[722,256] + b)
// Transposed-A smem + FFMA2.
// ============================================================
__global__ void __launch_bounds__(256) k_final(const float* __restrict__ Wao,
                                               const float* __restrict__ bao,
                                               float* __restrict__ out) {
    __shared__ float At[64*TPAD];   // transposed A chunk [k][r]
    __shared__ float Bs[64*64];
    const int tid = threadIdx.x;
    const int r0 = blockIdx.x * 64;
    const int c0 = blockIdx.y * 64;
    const int ty = tid >> 4, tx = tid & 15;

    unsigned long long acc[4][2];
#pragma unroll
    for (int r = 0; r < 4; r++) { acc[r][0] = 0ull; acc[r][1] = 0ull; }

    for (int k0 = 0; k0 < CATK; k0 += 64) {
        const int kc = (CATK - k0 < 64) ? (CATK - k0) : 64;
        for (int t = tid; t < 64*64; t += 256) {
            int r = t >> 6, k = t & 63;
            At[k*TPAD + r] = (k < kc) ? g_cat[(size_t)(r0 + r)*CATS + k0 + k] : 0.f;
        }
        for (int t = tid; t < 64*64; t += 256) {
            int k = t >> 6, c = t & 63;
            Bs[t] = (k < kc) ? Wao[(size_t)(k0 + k)*HID + c0 + c] : 0.f;
        }
        __syncthreads();
#pragma unroll 8
        for (int k = 0; k < 64; k++) {
            const float4 av = *reinterpret_cast<const float4*>(At + k*TPAD + ty*4);
            const unsigned long long* bp =
                reinterpret_cast<const unsigned long long*>(Bs + k*64 + tx*4);
            const unsigned long long b01 = bp[0], b23 = bp[1];
            const unsigned long long a0 = pk2(av.x), a1 = pk2(av.y),
                                     a2 = pk2(av.z), a3 = pk2(av.w);
            acc[0][0] = ffma2(a0, b01, acc[0][0]); acc[0][1] = ffma2(a0, b23, acc[0][1]);
            acc[1][0] = ffma2(a1, b01, acc[1][0]); acc[1][1] = ffma2(a1, b23, acc[1][1]);
            acc[2][0] = ffma2(a2, b01, acc[2][0]); acc[2][1] = ffma2(a2, b23, acc[2][1]);
            acc[3][0] = ffma2(a3, b01, acc[3][0]); acc[3][1] = ffma2(a3, b23, acc[3][1]);
        }
        __syncthreads();
    }

#pragma unroll
    for (int r = 0; r < 4; r++) {
        int row = r0 + ty*4 + r;
        const float2 v01 = upk2(acc[r][0]);
        const float2 v23 = upk2(acc[r][1]);
        const int col = c0 + tx*4;
        out[(size_t)row*HID + col    ] = fmaxf(v01.x + bao[col    ], 0.f);
        out[(size_t)row*HID + col + 1] = fmaxf(v01.y + bao[col + 1], 0.f);
        out[(size_t)row*HID + col + 2] = fmaxf(v23.x + bao[col + 2], 0.f);
        out[(size_t)row*HID + col + 3] = fmaxf(v23.y + bao[col + 3], 0.f);
    }
}

// ============================================================
extern "C" void kernel_launch(void* const* d_in, const int* in_sizes, int n_in,
                              void* d_out, int out_size) {
    const float* atom = (const float*)d_in[0];
    const float* path = (const float*)d_in[1];
    const float* mask = (const float*)d_in[2];
    const float* Wai  = (const float*)d_in[3];
    const float* Wah  = (const float*)d_in[4];
    const float* bah  = (const float*)d_in[5];
    const float* Wo   = (const float*)d_in[6];
    const float* bo   = (const float*)d_in[7];
    const float* Wmh  = (const float*)d_in[8];
    const float* bmh  = (const float*)d_in[9];
    const float* Wao  = (const float*)d_in[10];
    const float* bao  = (const float*)d_in[11];
    float* out = (float*)d_out;

    const int SMEM_B = (FP*TPAD  + FP*160) * 4;   //  93,024 B -> 2 CTAs/SM
    const int SMEM_P = (DKK*TPAD + DKK*160) * 4;  //  72,960 B -> 3 CTAs/SM
    cudaFuncSetAttribute(k_pathprojm, cudaFuncAttributeMaxDynamicSharedMemorySize, SMEM_B);
    cudaFuncSetAttribute(k_proj4,     cudaFuncAttributeMaxDynamicSharedMemorySize, SMEM_P);

    k_mask     <<<ROWS/8,       256>>>(mask);
    k_scan     <<<1,            256>>>();
    k_proj0    <<<dim3(32, 8),  256>>>(atom, Wai);
    k_pathprojm<<<PAIRS/64,     256, SMEM_B>>>(path, Wah, Wmh, bah);
    k_proj4    <<<dim3(256, 2), 256, SMEM_P>>>(Wah, Wmh);    // layer 1 projections
    k_attn     <<<ROWS,         256>>>(Wo, bo, bmh, 0);      // layer 1 -> g_atomh
    k_proj4    <<<dim3(256, 2), 256, SMEM_P>>>(Wah, Wmh);    // layer 2 projections
    k_attn     <<<ROWS,         256>>>(Wo, bo, bmh, 1);      // layer 2 -> g_cat
    k_final    <<<dim3(32, 4),  256>>>(Wao, bao, out);
}

// round 12
// speedup vs baseline: 1.8953x; 1.0464x over previous
#include <cuda_runtime.h>

// ---------------- problem constants ----------------
#define BB      32
#define NN      64
#define FA      82
#define FP      102
#define HH      8
#define DKK     80
#define HID     256
#define HB      (HH*BB)        // 256
#define ROWS    (BB*NN)        // 2048
#define PAIRS   (BB*NN*NN)     // 131072
#define CATK    722
#define CATS    724            // padded row stride for concat matrix
#define TPAD    68             // transposed-A smem row stride (16B multiple)

// ---------------- f32x2 packed helpers (sm_103a FFMA2) ----------------
__device__ __forceinline__ unsigned long long pk2(float x) {
    unsigned long long d;
    asm("mov.b64 %0, {%1, %1};" : "=l"(d) : "r"(__float_as_uint(x)));
    return d;
}
__device__ __forceinline__ unsigned long long ffma2(unsigned long long a,
                                                    unsigned long long b,
                                                    unsigned long long c) {
    unsigned long long d;
    asm("fma.rn.f32x2 %0, %1, %2, %3;" : "=l"(d) : "l"(a), "l"(b), "l"(c));
    return d;
}
__device__ __forceinline__ float2 upk2(unsigned long long d) {
    unsigned lo, hi;
    asm("mov.b64 {%0, %1}, %2;" : "=r"(lo), "=r"(hi) : "l"(d));
    return make_float2(__uint_as_float(lo), __uint_as_float(hi));
}

// ---------------- device scratch (no allocations allowed) ----------------
__device__ float g_Pc[(size_t)PAIRS*DKK];     // compacted: (path@W1p)+b_attn_h
__device__ float g_Qc[(size_t)PAIRS*DKK];     // compacted: path@W2p
__device__ float g_atom0[(size_t)HB*NN*DKK];  // atom_h0 [h*B+b, n, d]
__device__ float g_atomh[(size_t)HB*NN*DKK];  // current atom_h
__device__ float g_u [(size_t)HB*NN*DKK];
__device__ float g_v [(size_t)HB*NN*DKK];
__device__ float g_ws[(size_t)HB*NN*DKK];
__device__ float g_w [(size_t)HB*NN*DKK];
__device__ float g_cat[(size_t)ROWS*CATS];    // [atom_input | merged heads]
__device__ int   g_cnt[ROWS];
__device__ int   g_start[ROWS+1];
__device__ int   g_jidx[ROWS*NN];

// ============================================================
// Kernel M: per-(b,i) active-j list via warp ballot.
// ============================================================
__global__ void __launch_bounds__(256) k_mask(const float* __restrict__ mask) {
    const int bi = blockIdx.x * 8 + (threadIdx.x >> 5);
    const int lane = threadIdx.x & 31;
    const float m0 = mask[(size_t)bi*NN + lane];
    const float m1 = mask[(size_t)bi*NN + 32 + lane];
    const unsigned b0 = __ballot_sync(0xffffffffu, m0 != 0.f);
    const unsigned b1 = __ballot_sync(0xffffffffu, m1 != 0.f);
    const unsigned lt = (1u << lane) - 1u;
    const int c0 = __popc(b0);
    if (m0 != 0.f) g_jidx[bi*NN + __popc(b0 & lt)] = lane;
    if (m1 != 0.f) g_jidx[bi*NN + c0 + __popc(b1 & lt)] = lane + 32;
    if (lane == 0) g_cnt[bi] = c0 + __popc(b1);
}

// ============================================================
// Kernel S: exclusive prefix sum of g_cnt[2048] -> g_start. One CTA.
// ============================================================
__global__ void __launch_bounds__(256) k_scan() {
    __shared__ int warp_sums[8];
    __shared__ int warp_off[8];
    const int tid = threadIdx.x;
    const int base = tid * 8;
    int v[8]; int tot = 0;
#pragma unroll
    for (int i = 0; i < 8; i++) { v[i] = g_cnt[base + i]; tot += v[i]; }
    const int lane = tid & 31, wid = tid >> 5;
    int x = tot;
#pragma unroll
    for (int o = 1; o < 32; o <<= 1) {
        int y = __shfl_up_sync(0xffffffffu, x, o);
        if (lane >= o) x += y;
    }
    if (lane == 31) warp_sums[wid] = x;
    __syncthreads();
    if (tid == 0) {
        int a = 0;
#pragma unroll
        for (int w = 0; w < 8; w++) { warp_off[w] = a; a += warp_sums[w]; }
        g_start[ROWS] = a;
    }
    __syncthreads();
    int a = x - tot + warp_off[wid];
#pragma unroll
    for (int i = 0; i < 8; i++) { g_start[base + i] = a; a += v[i]; }
}

// ============================================================
// Kernel A: atom_h0 = atom_input @ W_atom_i (init g_atomh, g_cat[:, :82])
// ============================================================
__global__ void __launch_bounds__(256) k_proj0(const float* __restrict__ atom,
                                               const float* __restrict__ Wai) {
    __shared__ float As[64*FA];
    __shared__ float Bs[FA*DKK];
    const int tid = threadIdx.x;
    const int r0 = blockIdx.x * 64;
    const int h  = blockIdx.y;
    const int c0 = h * DKK;

    for (int i = tid; i < 64*FA; i += 256) As[i] = atom[(size_t)r0*FA + i];
    for (int i = tid; i < FA*DKK; i += 256) {
        int k = i / DKK, c = i % DKK;
        Bs[i] = Wai[(size_t)k*(HH*DKK) + c0 + c];
    }
    __syncthreads();

    const int ty = tid >> 4, tx = tid & 15;
    float acc[4][5];
#pragma unroll
    for (int r = 0; r < 4; r++)
#pragma unroll
        for (int c = 0; c < 5; c++) acc[r][c] = 0.f;

    for (int k = 0; k < FA; k++) {
        float a[4], b[5];
#pragma unroll
        for (int r = 0; r < 4; r++) a[r] = As[(ty*4+r)*FA + k];
#pragma unroll
        for (int c = 0; c < 5; c++) b[c] = Bs[k*DKK + tx*5 + c];
#pragma unroll
        for (int r = 0; r < 4; r++)
#pragma unroll
            for (int c = 0; c < 5; c++) acc[r][c] += a[r]*b[c];
    }

#pragma unroll
    for (int r = 0; r < 4; r++) {
        int row = r0 + ty*4 + r;
#pragma unroll
        for (int c = 0; c < 5; c++) {
            int d = tx*5 + c;
            size_t o = ((size_t)h*ROWS + row)*DKK + d;
            g_atom0[o] = acc[r][c];
            g_atomh[o] = acc[r][c];
        }
    }
    if (blockIdx.y == 0) {
        for (int i = tid; i < 64*FA; i += 256)
            g_cat[(size_t)(r0 + i/FA)*CATS + (i % FA)] = As[i];
    }
}

// ============================================================
// Kernel B': masked path projection, TWO-PASS column halves.
// A staged once (transposed), B restaged per half. smem 60.4KB -> 3 CTAs/SM.
// Pass 0 -> P (cols 0..79, +bias); pass 1 -> Q (cols 80..159).
// ============================================================
__global__ void __launch_bounds__(256, 3) k_pathprojm(const float* __restrict__ path,
                                                      const float* __restrict__ Wah,
                                                      const float* __restrict__ Wmh,
                                                      const float* __restrict__ bah) {
    const int T = g_start[ROWS];
    const int t0 = blockIdx.x * 64;
    if (t0 >= T) return;

    extern __shared__ float sm[];
    float* At = sm;               // [FP][TPAD] transposed A (64 rows used)
    float* Bs = sm + FP*TPAD;     // [FP][80] current column half
    __shared__ int sPair[64];

    const int tid = threadIdx.x;

    // map slots -> pair index (binary search in g_start)
    if (tid < 64) {
        int t = t0 + tid; if (t >= T) t = T - 1;
        int lo = 0, hi = ROWS - 1;
        while (lo < hi) {
            int mid = (lo + hi + 1) >> 1;
            if (__ldg(&g_start[mid]) <= t) lo = mid; else hi = mid - 1;
        }
        int slot = t - __ldg(&g_start[lo]);
        sPair[tid] = lo*NN + g_jidx[lo*NN + slot];
    }
    // stage B half 0 (W1p columns 0..79)
    for (int i = tid; i < FP*80; i += 256) {
        int k = i / 80, c = i % 80;
        Bs[i] = Wah[(size_t)(160+k)*DKK + c];
    }
    __syncthreads();

    // gather A rows transposed: 4 threads per row, scalar scatter into At[k][row]
    {
        const int row = tid >> 2, part = tid & 3;
        const float2* src = reinterpret_cast<const float2*>(path) + (size_t)sPair[row]*51;
        const int q0 = part*13;
        const int q1 = (part == 3) ? 51 : q0 + 13;
        for (int q = q0; q < q1; q++) {
            float2 v = src[q];
            At[(2*q)  *TPAD + row] = v.x;
            At[(2*q+1)*TPAD + row] = v.y;
        }
    }
    __syncthreads();

    const int tx  = tid & 7;       // 10 cols each
    const int tyr = tid >> 3;      // 2 rows each (64 rows)

#pragma unroll
    for (int half = 0; half < 2; half++) {
        unsigned long long acc[2][5];
#pragma unroll
        for (int r = 0; r < 2; r++)
#pragma unroll
            for (int c = 0; c < 5; c++) acc[r][c] = 0ull;

#pragma unroll 2
        for (int k = 0; k < FP; k++) {
            const float2 af = *reinterpret_cast<const float2*>(At + k*TPAD + tyr*2);
            const unsigned long long a0 = pk2(af.x), a1 = pk2(af.y);
            const unsigned long long* bp =
                reinterpret_cast<const unsigned long long*>(Bs + k*80 + tx*10);
            unsigned long long b[5];
#pragma unroll
            for (int c = 0; c < 5; c++) b[c] = bp[c];
#pragma unroll
            for (int c = 0; c < 5; c++) {
                acc[0][c] = ffma2(a0, b[c], acc[0][c]);
                acc[1][c] = ffma2(a1, b[c], acc[1][c]);
            }
        }
        __syncthreads();   // everyone done reading Bs

        if (half == 0) {   // restage B half 1 (W2p columns)
            for (int i = tid; i < FP*80; i += 256) {
                int k = i / 80, c = i % 80;
                Bs[i] = Wmh[(size_t)(160+k)*DKK + c];
            }
        }

        // write this half's outputs
#pragma unroll
        for (int rr = 0; rr < 2; rr++) {
            const int t = t0 + tyr*2 + rr;
            if (t < T) {
#pragma unroll
                for (int c = 0; c < 5; c++) {
                    const int col = tx*10 + 2*c;
                    const float2 v = upk2(acc[rr][c]);
                    if (half == 0) {
                        g_Pc[(size_t)t*DKK + col]     = v.x + bah[col];
                        g_Pc[(size_t)t*DKK + col + 1] = v.y + bah[col + 1];
                    } else {
                        g_Qc[(size_t)t*DKK + col]     = v.x;
                        g_Qc[(size_t)t*DKK + col + 1] = v.y;
                    }
                }
            }
        }
        if (half == 0) __syncthreads();  // Bs restage visible before pass 1
    }
}

// ============================================================
// Kernel P: {u,v,ws,w} = g_atomh @ {W1a,W1b,W2a,W2b} picked by blockIdx.y.
// Tile = 64 rows x 80 cols. smem 47.4KB -> 4 CTAs/SM. Grid (256, 4).
// ============================================================
__global__ void __launch_bounds__(256, 4) k_proj4(const float* __restrict__ Wah,
                                                  const float* __restrict__ Wmh) {
    extern __shared__ float sm[];
    float* At = sm;               // [DKK][TPAD] transposed A (64 rows used)
    float* Bs = sm + DKK*TPAD;    // [DKK][80]
    const int tid = threadIdx.x;
    const size_t r0 = (size_t)blockIdx.x * 64;
    const int y = blockIdx.y;     // 0:u(W1a) 1:v(W1b) 2:ws(W2a) 3:w(W2b)

    // stage B: rows (y&1)*80 .. +79 of Wah (y<2) or Wmh (y>=2)
    {
        const float* Wsrc = ((y < 2) ? Wah : Wmh) + (size_t)((y & 1) * 80) * DKK;
        for (int i = tid; i < DKK*80; i += 256) {
            int k = i / 80, c = i % 80;
            Bs[i] = Wsrc[(size_t)k*DKK + c];
        }
    }
    // gather A transposed: 4 threads per row, 10 float2 each
    {
        const int row = tid >> 2, part = tid & 3;
        const float2* src = reinterpret_cast<const float2*>(g_atomh + (r0 + row)*DKK);
        const int q0 = part*10;
#pragma unroll
        for (int q = q0; q < q0 + 10; q++) {
            float2 v = src[q];
            At[(2*q)  *TPAD + row] = v.x;
            At[(2*q+1)*TPAD + row] = v.y;
        }
    }
    __syncthreads();

    const int tx  = tid & 7;      // 10 cols
    const int tyr = tid >> 3;     // 2 rows

    unsigned long long acc[2][5];
#pragma unroll
    for (int r = 0; r < 2; r++)
#pragma unroll
        for (int c = 0; c < 5; c++) acc[r][c] = 0ull;

#pragma unroll 2
    for (int k = 0; k < DKK; k++) {
        const float2 af = *reinterpret_cast<const float2*>(At + k*TPAD + tyr*2);
        const unsigned long long a0 = pk2(af.x), a1 = pk2(af.y);
        const unsigned long long* bp =
            reinterpret_cast<const unsigned long long*>(Bs + k*80 + tx*10);
        unsigned long long b[5];
#pragma unroll
        for (int c = 0; c < 5; c++) b[c] = bp[c];
#pragma unroll
        for (int c = 0; c < 5; c++) {
            acc[0][c] = ffma2(a0, b[c], acc[0][c]);
            acc[1][c] = ffma2(a1, b[c], acc[1][c]);
        }
    }

    float* dst = (y == 0) ? g_u : (y == 1) ? g_v : (y == 2) ? g_ws : g_w;
#pragma unroll
    for (int rr = 0; rr < 2; rr++) {
        const size_t row = r0 + tyr*2 + rr;
#pragma unroll
        for (int c = 0; c < 5; c++) {
            const int col = tx*10 + 2*c;
            const float2 v = upk2(acc[rr][c]);
            dst[row*DKK + col]     = v.x;
            dst[row*DKK + col + 1] = v.y;
        }
    }
}

// ============================================================
// Kernel C: message-passing layer over ACTIVE slots only. CTA=(b,i), warp=head.
// ============================================================
__global__ void __launch_bounds__(256) k_attn(const float* __restrict__ Wo,
                                              const float* __restrict__ bo,
                                              const float* __restrict__ bmsg,
                                              int mode) {
    __shared__ float sP[NN*DKK];
    __shared__ float sQ[NN*DKK];
    __shared__ float sSc[HH*NN];
    __shared__ float sPr[HH*NN];
    __shared__ int   sJ[NN];

    const int tid = threadIdx.x;
    const int bi = blockIdx.x;
    const int b = bi >> 6;
    const int cnt  = g_cnt[bi];
    const int base = g_start[bi];

    {
        const float4* ps = reinterpret_cast<const float4*>(g_Pc + (size_t)base*DKK);
        const float4* qs = reinterpret_cast<const float4*>(g_Qc + (size_t)base*DKK);
        float4* pd = reinterpret_cast<float4*>(sP);
        float4* qd = reinterpret_cast<float4*>(sQ);
        const int n4 = cnt * (DKK/4);
        for (int t = tid; t < n4; t += 256) { pd[t] = ps[t]; qd[t] = qs[t]; }
    }
    if (tid < cnt) sJ[tid] = g_jidx[bi*NN + tid];
    __syncthreads();

    const int h = tid >> 5, lane = tid & 31;
    const int hb = h*BB + b;
    const size_t base_i = ((size_t)hb*NN + (bi & 63))*DKK;

    const float* urow = g_u + base_i;
    const float u0 = urow[lane], u1 = urow[lane+32];
    const float u2 = (lane < 16) ? urow[64+lane] : 0.f;
    const float w0 = Wo[lane], w1 = Wo[lane+32];
    const float w2 = (lane < 16) ? Wo[64+lane] : 0.f;

    const float* V = g_v + (size_t)hb*NN*DKK;
    float* sc = sSc + h*NN;

    int s = 0;
    for (; s + 1 < cnt; s += 2) {
        const float* vrA = V + (size_t)sJ[s]*DKK;
        const float* vrB = V + (size_t)sJ[s+1]*DKK;
        float A0 = vrA[lane], A1 = vrA[lane+32];
        float B0 = vrB[lane], B1 = vrB[lane+32];
        float A2 = 0.f, B2 = 0.f;
        if (lane < 16) { A2 = vrA[64+lane]; B2 = vrB[64+lane]; }
        float hA0 = u0 + A0 + sP[s*DKK + lane];
        float hA1 = u1 + A1 + sP[s*DKK + 32 + lane];
        float hA2 = (lane < 16) ? (u2 + A2 + sP[s*DKK + 64 + lane]) : 0.f;
        float hB0 = u0 + B0 + sP[(s+1)*DKK + lane];
        float hB1 = u1 + B1 + sP[(s+1)*DKK + 32 + lane];
        float hB2 = (lane < 16) ? (u2 + B2 + sP[(s+1)*DKK + 64 + lane]) : 0.f;
        hA0 = hA0 > 0.f ? hA0 : 0.2f*hA0;  hB0 = hB0 > 0.f ? hB0 : 0.2f*hB0;
        hA1 = hA1 > 0.f ? hA1 : 0.2f*hA1;  hB1 = hB1 > 0.f ? hB1 : 0.2f*hB1;
        hA2 = hA2 > 0.f ? hA2 : 0.2f*hA2;  hB2 = hB2 > 0.f ? hB2 : 0.2f*hB2;
        float sA = hA0*w0 + hA1*w1 + hA2*w2;
        float sB = hB0*w0 + hB1*w1 + hB2*w2;
#pragma unroll
        for (int o = 16; o >= 1; o >>= 1) {
            sA += __shfl_xor_sync(0xffffffffu, sA, o);
            sB += __shfl_xor_sync(0xffffffffu, sB, o);
        }
        if (lane == 0) { sc[s] = sA; sc[s+1] = sB; }
    }
    for (; s < cnt; s++) {
        const float* vr = V + (size_t)sJ[s]*DKK;
        float h0 = u0 + vr[lane]    + sP[s*DKK + lane];
        float h1 = u1 + vr[lane+32] + sP[s*DKK + 32 + lane];
        float h2 = 0.f;
        if (lane < 16) h2 = u2 + vr[64+lane] + sP[s*DKK + 64 + lane];
        h0 = h0 > 0.f ? h0 : 0.2f*h0;
        h1 = h1 > 0.f ? h1 : 0.2f*h1;
        h2 = h2 > 0.f ? h2 : 0.2f*h2;
        float sv = h0*w0 + h1*w1 + h2*w2;
#pragma unroll
        for (int o = 16; o >= 1; o >>= 1) sv += __shfl_xor_sync(0xffffffffu, sv, o);
        if (lane == 0) sc[s] = sv;
    }
    __syncwarp();

    const float bov = bo[0];
    float s0 = (lane      < cnt) ? sc[lane]      + bov : -1e30f;
    float s1 = (lane + 32 < cnt) ? sc[lane + 32] + bov : -1e30f;
    float mx = fmaxf(s0, s1);
#pragma unroll
    for (int o = 16; o >= 1; o >>= 1) mx = fmaxf(mx, __shfl_xor_sync(0xffffffffu, mx, o));
    if (cnt < NN) mx = fmaxf(mx, 0.f);
    float e0 = (lane      < cnt) ? __expf(s0 - mx) : 0.f;
    float e1 = (lane + 32 < cnt) ? __expf(s1 - mx) : 0.f;
    float tot = e0 + e1;
#pragma unroll
    for (int o = 16; o >= 1; o >>= 1) tot += __shfl_xor_sync(0xffffffffu, tot, o);
    const float inv = 1.f / (tot + 1e-20f);
    sPr[h*NN + lane]      = e0 * inv;
    sPr[h*NN + lane + 32] = e1 * inv;
    const float S = tot * inv;
    __syncwarp();

    const float* W_ = g_w + (size_t)hb*NN*DKK;
    const float* pr = sPr + h*NN;
    float a0 = 0.f, a1 = 0.f, a2 = 0.f;
    s = 0;
    for (; s + 1 < cnt; s += 2) {
        const float pA = pr[s], pB = pr[s+1];
        const float* wrA = W_ + (size_t)sJ[s]*DKK;
        const float* wrB = W_ + (size_t)sJ[s+1]*DKK;
        float A0 = wrA[lane], A1 = wrA[lane+32];
        float B0 = wrB[lane], B1 = wrB[lane+32];
        a0 += pA * (A0 + sQ[s*DKK + lane]);
        a1 += pA * (A1 + sQ[s*DKK + 32 + lane]);
        a0 += pB * (B0 + sQ[(s+1)*DKK + lane]);
        a1 += pB * (B1 + sQ[(s+1)*DKK + 32 + lane]);
        if (lane < 16) {
            a2 += pA * (wrA[64+lane] + sQ[s*DKK + 64 + lane]);
            a2 += pB * (wrB[64+lane] + sQ[(s+1)*DKK + 64 + lane]);
        }
    }
    for (; s < cnt; s++) {
        const float p = pr[s];
        const float* wr = W_ + (size_t)sJ[s]*DKK;
        a0 += p * (wr[lane]    + sQ[s*DKK + lane]);
        a1 += p * (wr[lane+32] + sQ[s*DKK + 32 + lane]);
        if (lane < 16) a2 += p * (wr[64+lane] + sQ[s*DKK + 64 + lane]);
    }

    const float* wsr = g_ws   + base_i;
    const float* a0r = g_atom0 + base_i;
    float n0 = fmaxf(S*wsr[lane]    + a0 + bmsg[lane]    + a0r[lane],    0.f);
    float n1 = fmaxf(S*wsr[lane+32] + a1 + bmsg[lane+32] + a0r[lane+32], 0.f);
    float n2 = 0.f;
    if (lane < 16) n2 = fmaxf(S*wsr[64+lane] + a2 + bmsg[64+lane] + a0r[64+lane], 0.f);

    if (mode == 0) {
        float* o = g_atomh + base_i;
        o[lane] = n0; o[lane+32] = n1; if (lane < 16) o[64+lane] = n2;
    } else {
        float* o = g_cat + (size_t)bi*CATS + FA + h*DKK;
        o[lane] = n0; o[lane+32] = n1; if (lane < 16) o[64+lane] = n2;
    }
}

// ============================================================
// Kernel E: out = relu(g_cat[2048,722] @ W_atom_o[722,256] + b)
// Transposed-A smem + FFMA2.
// ============================================================
__global__ void __launch_bounds__(256) k_final(const float* __restrict__ Wao,
                                               const float* __restrict__ bao,
                                               float* __restrict__ out) {
    __shared__ float At[64*TPAD];   // transposed A chunk [k][r]
    __shared__ float Bs[64*64];
    const int tid = threadIdx.x;
    const int r0 = blockIdx.x * 64;
    const int c0 = blockIdx.y * 64;
    const int ty = tid >> 4, tx = tid & 15;

    unsigned long long acc[4][2];
#pragma unroll
    for (int r = 0; r < 4; r++) { acc[r][0] = 0ull; acc[r][1] = 0ull; }

    for (int k0 = 0; k0 < CATK; k0 += 64) {
        const int kc = (CATK - k0 < 64) ? (CATK - k0) : 64;
        for (int t = tid; t < 64*64; t += 256) {
            int r = t >> 6, k = t & 63;
            At[k*TPAD + r] = (k < kc) ? g_cat[(size_t)(r0 + r)*CATS + k0 + k] : 0.f;
        }
        for (int t = tid; t < 64*64; t += 256) {
            int k = t >> 6, c = t & 63;
            Bs[t] = (k < kc) ? Wao[(size_t)(k0 + k)*HID + c0 + c] : 0.f;
        }
        __syncthreads();
#pragma unroll 8
        for (int k = 0; k < 64; k++) {
            const float4 av = *reinterpret_cast<const float4*>(At + k*TPAD + ty*4);
            const unsigned long long* bp =
                reinterpret_cast<const unsigned long long*>(Bs + k*64 + tx*4);
            const unsigned long long b01 = bp[0], b23 = bp[1];
            const unsigned long long a0 = pk2(av.x), a1 = pk2(av.y),
                                     a2 = pk2(av.z), a3 = pk2(av.w);
            acc[0][0] = ffma2(a0, b01, acc[0][0]); acc[0][1] = ffma2(a0, b23, acc[0][1]);
            acc[1][0] = ffma2(a1, b01, acc[1][0]); acc[1][1] = ffma2(a1, b23, acc[1][1]);
            acc[2][0] = ffma2(a2, b01, acc[2][0]); acc[2][1] = ffma2(a2, b23, acc[2][1]);
            acc[3][0] = ffma2(a3, b01, acc[3][0]); acc[3][1] = ffma2(a3, b23, acc[3][1]);
        }
        __syncthreads();
    }

#pragma unroll
    for (int r = 0; r < 4; r++) {
        int row = r0 + ty*4 + r;
        const float2 v01 = upk2(acc[r][0]);
        const float2 v23 = upk2(acc[r][1]);
        const int col = c0 + tx*4;
        out[(size_t)row*HID + col    ] = fmaxf(v01.x + bao[col    ], 0.f);
        out[(size_t)row*HID + col + 1] = fmaxf(v01.y + bao[col + 1], 0.f);
        out[(size_t)row*HID + col + 2] = fmaxf(v23.x + bao[col + 2], 0.f);
        out[(size_t)row*HID + col + 3] = fmaxf(v23.y + bao[col + 3], 0.f);
    }
}

// ============================================================
extern "C" void kernel_launch(void* const* d_in, const int* in_sizes, int n_in,
                              void* d_out, int out_size) {
    const float* atom = (const float*)d_in[0];
    const float* path = (const float*)d_in[1];
    const float* mask = (const float*)d_in[2];
    const float* Wai  = (const float*)d_in[3];
    const float* Wah  = (const float*)d_in[4];
    const float* bah  = (const float*)d_in[5];
    const float* Wo   = (const float*)d_in[6];
    const float* bo   = (const float*)d_in[7];
    const float* Wmh  = (const float*)d_in[8];
    const float* bmh  = (const float*)d_in[9];
    const float* Wao  = (const float*)d_in[10];
    const float* bao  = (const float*)d_in[11];
    float* out = (float*)d_out;

    const int SMEM_B = (FP*TPAD  + FP*80) * 4;    //  60,384 B -> 3 CTAs/SM
    const int SMEM_P = (DKK*TPAD + DKK*80) * 4;   //  47,360 B -> 4 CTAs/SM
    cudaFuncSetAttribute(k_pathprojm, cudaFuncAttributeMaxDynamicSharedMemorySize, SMEM_B);
    cudaFuncSetAttribute(k_proj4,     cudaFuncAttributeMaxDynamicSharedMemorySize, SMEM_P);

    k_mask     <<<ROWS/8,       256>>>(mask);
    k_scan     <<<1,            256>>>();
    k_proj0    <<<dim3(32, 8),  256>>>(atom, Wai);
    k_pathprojm<<<PAIRS/64,     256, SMEM_B>>>(path, Wah, Wmh, bah);
    k_proj4    <<<dim3(256, 4), 256, SMEM_P>>>(Wah, Wmh);    // layer 1 projections
    k_attn     <<<ROWS,         256>>>(Wo, bo, bmh, 0);      // layer 1 -> g_atomh
    k_proj4    <<<dim3(256, 4), 256, SMEM_P>>>(Wah, Wmh);    // layer 2 projections
    k_attn     <<<ROWS,         256>>>(Wo, bo, bmh, 1);      // layer 2 -> g_cat
    k_final    <<<dim3(32, 4),  256>>>(Wao, bao, out);
}

// round 13
// speedup vs baseline: 1.9874x; 1.0486x over previous
#include <cuda_runtime.h>

// ---------------- problem constants ----------------
#define BB      32
#define NN      64
#define FA      82
#define FP      102
#define HH      8
#define DKK     80
#define HID     256
#define HB      (HH*BB)        // 256
#define ROWS    (BB*NN)        // 2048
#define PAIRS   (BB*NN*NN)     // 131072
#define CATK    722
#define CATS    724            // padded row stride for concat matrix
#define TPAD    68             // transposed-A smem row stride (16B multiple)

// ---------------- f32x2 packed helpers (sm_103a FFMA2) ----------------
__device__ __forceinline__ unsigned long long pk2(float x) {
    unsigned long long d;
    asm("mov.b64 %0, {%1, %1};" : "=l"(d) : "r"(__float_as_uint(x)));
    return d;
}
__device__ __forceinline__ unsigned long long ffma2(unsigned long long a,
                                                    unsigned long long b,
                                                    unsigned long long c) {
    unsigned long long d;
    asm("fma.rn.f32x2 %0, %1, %2, %3;" : "=l"(d) : "l"(a), "l"(b), "l"(c));
    return d;
}
__device__ __forceinline__ float2 upk2(unsigned long long d) {
    unsigned lo, hi;
    asm("mov.b64 {%0, %1}, %2;" : "=r"(lo), "=r"(hi) : "l"(d));
    return make_float2(__uint_as_float(lo), __uint_as_float(hi));
}

// ---------------- device scratch (no allocations allowed) ----------------
__device__ float g_Pc[(size_t)PAIRS*DKK];     // compacted: (path@W1p)+b_attn_h
__device__ float g_Qc[(size_t)PAIRS*DKK];     // compacted: path@W2p
__device__ float g_atom0[(size_t)HB*NN*DKK];  // atom_h0 [h*B+b, n, d]
__device__ float g_atomh[(size_t)HB*NN*DKK];  // current atom_h
__device__ float g_u [(size_t)HB*NN*DKK];
__device__ float g_v [(size_t)HB*NN*DKK];
__device__ float g_ws[(size_t)HB*NN*DKK];
__device__ float g_w [(size_t)HB*NN*DKK];
__device__ float g_cat[(size_t)ROWS*CATS];    // [atom_input | merged heads]
__device__ int   g_cnt[ROWS];
__device__ int   g_start[ROWS+1];
__device__ int   g_jidx[ROWS*NN];

// ============================================================
// Kernel M: per-(b,i) active-j list via warp ballot.
// ============================================================
__global__ void __launch_bounds__(256) k_mask(const float* __restrict__ mask) {
    const int bi = blockIdx.x * 8 + (threadIdx.x >> 5);
    const int lane = threadIdx.x & 31;
    const float m0 = mask[(size_t)bi*NN + lane];
    const float m1 = mask[(size_t)bi*NN + 32 + lane];
    const unsigned b0 = __ballot_sync(0xffffffffu, m0 != 0.f);
    const unsigned b1 = __ballot_sync(0xffffffffu, m1 != 0.f);
    const unsigned lt = (1u << lane) - 1u;
    const int c0 = __popc(b0);
    if (m0 != 0.f) g_jidx[bi*NN + __popc(b0 & lt)] = lane;
    if (m1 != 0.f) g_jidx[bi*NN + c0 + __popc(b1 & lt)] = lane + 32;
    if (lane == 0) g_cnt[bi] = c0 + __popc(b1);
}

// ============================================================
// Kernel S: exclusive prefix sum of g_cnt[2048] -> g_start. One CTA.
// ============================================================
__global__ void __launch_bounds__(256) k_scan() {
    __shared__ int warp_sums[8];
    __shared__ int warp_off[8];
    const int tid = threadIdx.x;
    const int base = tid * 8;
    int v[8]; int tot = 0;
#pragma unroll
    for (int i = 0; i < 8; i++) { v[i] = g_cnt[base + i]; tot += v[i]; }
    const int lane = tid & 31, wid = tid >> 5;
    int x = tot;
#pragma unroll
    for (int o = 1; o < 32; o <<= 1) {
        int y = __shfl_up_sync(0xffffffffu, x, o);
        if (lane >= o) x += y;
    }
    if (lane == 31) warp_sums[wid] = x;
    __syncthreads();
    if (tid == 0) {
        int a = 0;
#pragma unroll
        for (int w = 0; w < 8; w++) { warp_off[w] = a; a += warp_sums[w]; }
        g_start[ROWS] = a;
    }
    __syncthreads();
    int a = x - tot + warp_off[wid];
#pragma unroll
    for (int i = 0; i < 8; i++) { g_start[base + i] = a; a += v[i]; }
}

// ============================================================
// Kernel A: atom_h0 = atom_input @ W_atom_i (init g_atomh, g_cat[:, :82])
// ============================================================
__global__ void __launch_bounds__(256) k_proj0(const float* __restrict__ atom,
                                               const float* __restrict__ Wai) {
    __shared__ float As[64*FA];
    __shared__ float Bs[FA*DKK];
    const int tid = threadIdx.x;
    const int r0 = blockIdx.x * 64;
    const int h  = blockIdx.y;
    const int c0 = h * DKK;

    for (int i = tid; i < 64*FA; i += 256) As[i] = atom[(size_t)r0*FA + i];
    for (int i = tid; i < FA*DKK; i += 256) {
        int k = i / DKK, c = i % DKK;
        Bs[i] = Wai[(size_t)k*(HH*DKK) + c0 + c];
    }
    __syncthreads();

    const int ty = tid >> 4, tx = tid & 15;
    float acc[4][5];
#pragma unroll
    for (int r = 0; r < 4; r++)
#pragma unroll
        for (int c = 0; c < 5; c++) acc[r][c] = 0.f;

    for (int k = 0; k < FA; k++) {
        float a[4], b[5];
#pragma unroll
        for (int r = 0; r < 4; r++) a[r] = As[(ty*4+r)*FA + k];
#pragma unroll
        for (int c = 0; c < 5; c++) b[c] = Bs[k*DKK + tx*5 + c];
#pragma unroll
        for (int r = 0; r < 4; r++)
#pragma unroll
            for (int c = 0; c < 5; c++) acc[r][c] += a[r]*b[c];
    }

#pragma unroll
    for (int r = 0; r < 4; r++) {
        int row = r0 + ty*4 + r;
#pragma unroll
        for (int c = 0; c < 5; c++) {
            int d = tx*5 + c;
            size_t o = ((size_t)h*ROWS + row)*DKK + d;
            g_atom0[o] = acc[r][c];
            g_atomh[o] = acc[r][c];
        }
    }
    if (blockIdx.y == 0) {
        for (int i = tid; i < 64*FA; i += 256)
            g_cat[(size_t)(r0 + i/FA)*CATS + (i % FA)] = As[i];
    }
}

// ============================================================
// Kernel B': masked path projection. 64 slots x 160 cols, single pass,
// transposed-A smem, FFMA2, EXPLICIT k+1 PREFETCH pipeline.
// smem 93KB -> 2 CTAs/SM; regs free to ~90 for the pipeline.
// ============================================================
__global__ void __launch_bounds__(256) k_pathprojm(const float* __restrict__ path,
                                                   const float* __restrict__ Wah,
                                                   const float* __restrict__ Wmh,
                                                   const float* __restrict__ bah) {
    const int T = g_start[ROWS];
    const int t0 = blockIdx.x * 64;
    if (t0 >= T) return;

    extern __shared__ float sm[];
    float* At = sm;               // [FP][TPAD] transposed A (64 rows used)
    float* Bs = sm + FP*TPAD;     // [FP][160]
    __shared__ int sPair[64];

    const int tid = threadIdx.x;

    for (int i = tid; i < FP*160; i += 256) {
        int k = i / 160, c = i % 160;
        Bs[i] = (c < DKK) ? Wah[(size_t)(160+k)*DKK + c]
                          : Wmh[(size_t)(160+k)*DKK + (c - DKK)];
    }
    if (tid < 64) {
        int t = t0 + tid; if (t >= T) t = T - 1;
        int lo = 0, hi = ROWS - 1;
        while (lo < hi) {
            int mid = (lo + hi + 1) >> 1;
            if (__ldg(&g_start[mid]) <= t) lo = mid; else hi = mid - 1;
        }
        int slot = t - __ldg(&g_start[lo]);
        sPair[tid] = lo*NN + g_jidx[lo*NN + slot];
    }
    __syncthreads();

    // gather A rows transposed: 4 threads per row
    {
        const int row = tid >> 2, part = tid & 3;
        const float2* src = reinterpret_cast<const float2*>(path) + (size_t)sPair[row]*51;
        const int q0 = part*13;
        const int q1 = (part == 3) ? 51 : q0 + 13;
        for (int q = q0; q < q1; q++) {
            float2 v = src[q];
            At[(2*q)  *TPAD + row] = v.x;
            At[(2*q+1)*TPAD + row] = v.y;
        }
    }
    __syncthreads();

    const int ty = tid >> 4, tx = tid & 15;   // 4 rows x 10 cols per thread
    unsigned long long acc[4][5];
#pragma unroll
    for (int r = 0; r < 4; r++)
#pragma unroll
        for (int c = 0; c < 5; c++) acc[r][c] = 0ull;

    // software pipeline: prefetch k+1 while computing k
    float4 a_cur = *reinterpret_cast<const float4*>(At + 0*TPAD + ty*4);
    unsigned long long b_cur[5];
    {
        const unsigned long long* bp =
            reinterpret_cast<const unsigned long long*>(Bs + 0*160 + tx*10);
#pragma unroll
        for (int c = 0; c < 5; c++) b_cur[c] = bp[c];
    }

#pragma unroll 2
    for (int k = 0; k < FP; k++) {
        const int kn = (k + 1 < FP) ? k + 1 : k;   // in-bounds prefetch index
        const float4 a_nxt = *reinterpret_cast<const float4*>(At + kn*TPAD + ty*4);
        unsigned long long b_nxt[5];
        const unsigned long long* bp =
            reinterpret_cast<const unsigned long long*>(Bs + kn*160 + tx*10);
#pragma unroll
        for (int c = 0; c < 5; c++) b_nxt[c] = bp[c];

        const unsigned long long a0 = pk2(a_cur.x), a1 = pk2(a_cur.y),
                                 a2 = pk2(a_cur.z), a3 = pk2(a_cur.w);
#pragma unroll
        for (int c = 0; c < 5; c++) {
            acc[0][c] = ffma2(a0, b_cur[c], acc[0][c]);
            acc[1][c] = ffma2(a1, b_cur[c], acc[1][c]);
            acc[2][c] = ffma2(a2, b_cur[c], acc[2][c]);
            acc[3][c] = ffma2(a3, b_cur[c], acc[3][c]);
        }
        a_cur = a_nxt;
#pragma unroll
        for (int c = 0; c < 5; c++) b_cur[c] = b_nxt[c];
    }

#pragma unroll
    for (int r = 0; r < 4; r++) {
        int t = t0 + ty*4 + r;
        if (t >= T) continue;
#pragma unroll
        for (int c = 0; c < 5; c++) {
            const int col = tx*10 + 2*c;       // chunk never straddles col 80
            const float2 v = upk2(acc[r][c]);
            if (col < DKK) {
                g_Pc[(size_t)t*DKK + col]     = v.x + bah[col];
                g_Pc[(size_t)t*DKK + col + 1] = v.y + bah[col + 1];
            } else {
                g_Qc[(size_t)t*DKK + (col - DKK)]     = v.x;
                g_Qc[(size_t)t*DKK + (col - DKK) + 1] = v.y;
            }
        }
    }
}

// ============================================================
// Kernel P: {u,v,ws,w} = g_atomh @ {W1a,W1b,W2a,W2b} picked by blockIdx.y.
// Tile = 64 rows x 80 cols. smem 47.4KB -> 4 CTAs/SM. Grid (256, 4).
// ============================================================
__global__ void __launch_bounds__(256, 4) k_proj4(const float* __restrict__ Wah,
                                                  const float* __restrict__ Wmh) {
    extern __shared__ float sm[];
    float* At = sm;               // [DKK][TPAD] transposed A (64 rows used)
    float* Bs = sm + DKK*TPAD;    // [DKK][80]
    const int tid = threadIdx.x;
    const size_t r0 = (size_t)blockIdx.x * 64;
    const int y = blockIdx.y;     // 0:u(W1a) 1:v(W1b) 2:ws(W2a) 3:w(W2b)

    {
        const float* Wsrc = ((y < 2) ? Wah : Wmh) + (size_t)((y & 1) * 80) * DKK;
        for (int i = tid; i < DKK*80; i += 256) {
            int k = i / 80, c = i % 80;
            Bs[i] = Wsrc[(size_t)k*DKK + c];
        }
    }
    {
        const int row = tid >> 2, part = tid & 3;
        const float2* src = reinterpret_cast<const float2*>(g_atomh + (r0 + row)*DKK);
        const int q0 = part*10;
#pragma unroll
        for (int q = q0; q < q0 + 10; q++) {
            float2 v = src[q];
            At[(2*q)  *TPAD + row] = v.x;
            At[(2*q+1)*TPAD + row] = v.y;
        }
    }
    __syncthreads();

    const int tx  = tid & 7;      // 10 cols
    const int tyr = tid >> 3;     // 2 rows

    unsigned long long acc[2][5];
#pragma unroll
    for (int r = 0; r < 2; r++)
#pragma unroll
        for (int c = 0; c < 5; c++) acc[r][c] = 0ull;

#pragma unroll 2
    for (int k = 0; k < DKK; k++) {
        const float2 af = *reinterpret_cast<const float2*>(At + k*TPAD + tyr*2);
        const unsigned long long a0 = pk2(af.x), a1 = pk2(af.y);
        const unsigned long long* bp =
            reinterpret_cast<const unsigned long long*>(Bs + k*80 + tx*10);
        unsigned long long b[5];
#pragma unroll
        for (int c = 0; c < 5; c++) b[c] = bp[c];
#pragma unroll
        for (int c = 0; c < 5; c++) {
            acc[0][c] = ffma2(a0, b[c], acc[0][c]);
            acc[1][c] = ffma2(a1, b[c], acc[1][c]);
        }
    }

    float* dst = (y == 0) ? g_u : (y == 1) ? g_v : (y == 2) ? g_ws : g_w;
#pragma unroll
    for (int rr = 0; rr < 2; rr++) {
        const size_t row = r0 + tyr*2 + rr;
#pragma unroll
        for (int c = 0; c < 5; c++) {
            const int col = tx*10 + 2*c;
            const float2 v = upk2(acc[rr][c]);
            dst[row*DKK + col]     = v.x;
            dst[row*DKK + col + 1] = v.y;
        }
    }
}

// ============================================================
// Kernel C: message-passing layer over ACTIVE slots only. CTA=(b,i), warp=head.
// Both slot loops unrolled x4 (interleaved shuffle chains / MLP-12 loads).
// ============================================================
__global__ void __launch_bounds__(256) k_attn(const float* __restrict__ Wo,
                                              const float* __restrict__ bo,
                                              const float* __restrict__ bmsg,
                                              int mode) {
    __shared__ float sP[NN*DKK];
    __shared__ float sQ[NN*DKK];
    __shared__ float sSc[HH*NN];
    __shared__ float sPr[HH*NN];
    __shared__ int   sJ[NN];

    const int tid = threadIdx.x;
    const int bi = blockIdx.x;
    const int b = bi >> 6;
    const int cnt  = g_cnt[bi];
    const int base = g_start[bi];

    {
        const float4* ps = reinterpret_cast<const float4*>(g_Pc + (size_t)base*DKK);
        const float4* qs = reinterpret_cast<const float4*>(g_Qc + (size_t)base*DKK);
        float4* pd = reinterpret_cast<float4*>(sP);
        float4* qd = reinterpret_cast<float4*>(sQ);
        const int n4 = cnt * (DKK/4);
        for (int t = tid; t < n4; t += 256) { pd[t] = ps[t]; qd[t] = qs[t]; }
    }
    if (tid < cnt) sJ[tid] = g_jidx[bi*NN + tid];
    __syncthreads();

    const int h = tid >> 5, lane = tid & 31;
    const int hb = h*BB + b;
    const size_t base_i = ((size_t)hb*NN + (bi & 63))*DKK;

    const float* urow = g_u + base_i;
    const float u0 = urow[lane], u1 = urow[lane+32];
    const float u2 = (lane < 16) ? urow[64+lane] : 0.f;
    const float w0 = Wo[lane], w1 = Wo[lane+32];
    const float w2 = (lane < 16) ? Wo[64+lane] : 0.f;

    const float* V = g_v + (size_t)hb*NN*DKK;
    float* sc = sSc + h*NN;

    // ---- pass 1: scores, x4 unrolled (4 interleaved shuffle chains) ----
    int s = 0;
    for (; s + 3 < cnt; s += 4) {
        float sv[4];
#pragma unroll
        for (int r = 0; r < 4; r++) {
            const float* vr = V + (size_t)sJ[s+r]*DKK;
            float h0 = u0 + vr[lane]    + sP[(s+r)*DKK + lane];
            float h1 = u1 + vr[lane+32] + sP[(s+r)*DKK + 32 + lane];
            float h2 = 0.f;
            if (lane < 16) h2 = u2 + vr[64+lane] + sP[(s+r)*DKK + 64 + lane];
            h0 = h0 > 0.f ? h0 : 0.2f*h0;
            h1 = h1 > 0.f ? h1 : 0.2f*h1;
            h2 = h2 > 0.f ? h2 : 0.2f*h2;
            sv[r] = h0*w0 + h1*w1 + h2*w2;
        }
#pragma unroll
        for (int o = 16; o >= 1; o >>= 1) {
#pragma unroll
            for (int r = 0; r < 4; r++)
                sv[r] += __shfl_xor_sync(0xffffffffu, sv[r], o);
        }
        if (lane == 0) {
            sc[s] = sv[0]; sc[s+1] = sv[1]; sc[s+2] = sv[2]; sc[s+3] = sv[3];
        }
    }
    for (; s < cnt; s++) {
        const float* vr = V + (size_t)sJ[s]*DKK;
        float h0 = u0 + vr[lane]    + sP[s*DKK + lane];
        float h1 = u1 + vr[lane+32] + sP[s*DKK + 32 + lane];
        float h2 = 0.f;
        if (lane < 16) h2 = u2 + vr[64+lane] + sP[s*DKK + 64 + lane];
        h0 = h0 > 0.f ? h0 : 0.2f*h0;
        h1 = h1 > 0.f ? h1 : 0.2f*h1;
        h2 = h2 > 0.f ? h2 : 0.2f*h2;
        float sv = h0*w0 + h1*w1 + h2*w2;
#pragma unroll
        for (int o = 16; o >= 1; o >>= 1) sv += __shfl_xor_sync(0xffffffffu, sv, o);
        if (lane == 0) sc[s] = sv;
    }
    __syncwarp();

    // ---- masked softmax (masked scores are exactly 0) ----
    const float bov = bo[0];
    float s0 = (lane      < cnt) ? sc[lane]      + bov : -1e30f;
    float s1 = (lane + 32 < cnt) ? sc[lane + 32] + bov : -1e30f;
    float mx = fmaxf(s0, s1);
#pragma unroll
    for (int o = 16; o >= 1; o >>= 1) mx = fmaxf(mx, __shfl_xor_sync(0xffffffffu, mx, o));
    if (cnt < NN) mx = fmaxf(mx, 0.f);
    float e0 = (lane      < cnt) ? __expf(s0 - mx) : 0.f;
    float e1 = (lane + 32 < cnt) ? __expf(s1 - mx) : 0.f;
    float tot = e0 + e1;
#pragma unroll
    for (int o = 16; o >= 1; o >>= 1) tot += __shfl_xor_sync(0xffffffffu, tot, o);
    const float inv = 1.f / (tot + 1e-20f);
    sPr[h*NN + lane]      = e0 * inv;
    sPr[h*NN + lane + 32] = e1 * inv;
    const float S = tot * inv;
    __syncwarp();

    // ---- pass 2: weighted message accumulation, x4 unrolled ----
    const float* W_ = g_w + (size_t)hb*NN*DKK;
    const float* pr = sPr + h*NN;
    float a0 = 0.f, a1 = 0.f, a2 = 0.f;
    s = 0;
    for (; s + 3 < cnt; s += 4) {
#pragma unroll
        for (int r = 0; r < 4; r++) {
            const float p = pr[s+r];
            const float* wr = W_ + (size_t)sJ[s+r]*DKK;
            a0 += p * (wr[lane]    + sQ[(s+r)*DKK + lane]);
            a1 += p * (wr[lane+32] + sQ[(s+r)*DKK + 32 + lane]);
            if (lane < 16) a2 += p * (wr[64+lane] + sQ[(s+r)*DKK + 64 + lane]);
        }
    }
    for (; s < cnt; s++) {
        const float p = pr[s];
        const float* wr = W_ + (size_t)sJ[s]*DKK;
        a0 += p * (wr[lane]    + sQ[s*DKK + lane]);
        a1 += p * (wr[lane+32] + sQ[s*DKK + 32 + lane]);
        if (lane < 16) a2 += p * (wr[64+lane] + sQ[s*DKK + 64 + lane]);
    }

    const float* wsr = g_ws   + base_i;
    const float* a0r = g_atom0 + base_i;
    float n0 = fmaxf(S*wsr[lane]    + a0 + bmsg[lane]    + a0r[lane],    0.f);
    float n1 = fmaxf(S*wsr[lane+32] + a1 + bmsg[lane+32] + a0r[lane+32], 0.f);
    float n2 = 0.f;
    if (lane < 16) n2 = fmaxf(S*wsr[64+lane] + a2 + bmsg[64+lane] + a0r[64+lane], 0.f);

    if (mode == 0) {
        float* o = g_atomh + base_i;
        o[lane] = n0; o[lane+32] = n1; if (lane < 16) o[64+lane] = n2;
    } else {
        float* o = g_cat + (size_t)bi*CATS + FA + h*DKK;
        o[lane] = n0; o[lane+32] = n1; if (lane < 16) o[64+lane] = n2;
    }
}

// ============================================================
// Kernel E: out = relu(g_cat[2048,722] @ W_atom_o[722,256] + b)
// Transposed-A smem + FFMA2.
// ============================================================
__global__ void __launch_bounds__(256) k_final(const float* __restrict__ Wao,
                                               const float* __restrict__ bao,
                                               float* __restrict__ out) {
    __shared__ float At[64*TPAD];   // transposed A chunk [k][r]
    __shared__ float Bs[64*64];
    const int tid = threadIdx.x;
    const int r0 = blockIdx.x * 64;
    const int c0 = blockIdx.y * 64;
    const int ty = tid >> 4, tx = tid & 15;

    unsigned long long acc[4][2];
#pragma unroll
    for (int r = 0; r < 4; r++) { acc[r][0] = 0ull; acc[r][1] = 0ull; }

    for (int k0 = 0; k0 < CATK; k0 += 64) {
        const int kc = (CATK - k0 < 64) ? (CATK - k0) : 64;
        for (int t = tid; t < 64*64; t += 256) {
            int r = t >> 6, k = t & 63;
            At[k*TPAD + r] = (k < kc) ? g_cat[(size_t)(r0 + r)*CATS + k0 + k] : 0.f;
        }
        for (int t = tid; t < 64*64; t += 256) {
            int k = t >> 6, c = t & 63;
            Bs[t] = (k < kc) ? Wao[(size_t)(k0 + k)*HID + c0 + c] : 0.f;
        }
        __syncthreads();
#pragma unroll 8
        for (int k = 0; k < 64; k++) {
            const float4 av = *reinterpret_cast<const float4*>(At + k*TPAD + ty*4);
            const unsigned long long* bp =
                reinterpret_cast<const unsigned long long*>(Bs + k*64 + tx*4);
            const unsigned long long b01 = bp[0], b23 = bp[1];
            const unsigned long long a0 = pk2(av.x), a1 = pk2(av.y),
                                     a2 = pk2(av.z), a3 = pk2(av.w);
            acc[0][0] = ffma2(a0, b01, acc[0][0]); acc[0][1] = ffma2(a0, b23, acc[0][1]);
            acc[1][0] = ffma2(a1, b01, acc[1][0]); acc[1][1] = ffma2(a1, b23, acc[1][1]);
            acc[2][0] = ffma2(a2, b01, acc[2][0]); acc[2][1] = ffma2(a2, b23, acc[2][1]);
            acc[3][0] = ffma2(a3, b01, acc[3][0]); acc[3][1] = ffma2(a3, b23, acc[3][1]);
        }
        __syncthreads();
    }

#pragma unroll
    for (int r = 0; r < 4; r++) {
        int row = r0 + ty*4 + r;
        const float2 v01 = upk2(acc[r][0]);
        const float2 v23 = upk2(acc[r][1]);
        const int col = c0 + tx*4;
        out[(size_t)row*HID + col    ] = fmaxf(v01.x + bao[col    ], 0.f);
        out[(size_t)row*HID + col + 1] = fmaxf(v01.y + bao[col + 1], 0.f);
        out[(size_t)row*HID + col + 2] = fmaxf(v23.x + bao[col + 2], 0.f);
        out[(size_t)row*HID + col + 3] = fmaxf(v23.y + bao[col + 3], 0.f);
    }
}

// ============================================================
extern "C" void kernel_launch(void* const* d_in, const int* in_sizes, int n_in,
                              void* d_out, int out_size) {
    const float* atom = (const float*)d_in[0];
    const float* path = (const float*)d_in[1];
    const float* mask = (const float*)d_in[2];
    const float* Wai  = (const float*)d_in[3];
    const float* Wah  = (const float*)d_in[4];
    const float* bah  = (const float*)d_in[5];
    const float* Wo   = (const float*)d_in[6];
    const float* bo   = (const float*)d_in[7];
    const float* Wmh  = (const float*)d_in[8];
    const float* bmh  = (const float*)d_in[9];
    const float* Wao  = (const float*)d_in[10];
    const float* bao  = (const float*)d_in[11];
    float* out = (float*)d_out;

    const int SMEM_B = (FP*TPAD  + FP*160) * 4;   //  93,024 B -> 2 CTAs/SM
    const int SMEM_P = (DKK*TPAD + DKK*80) * 4;   //  47,360 B -> 4 CTAs/SM
    cudaFuncSetAttribute(k_pathprojm, cudaFuncAttributeMaxDynamicSharedMemorySize, SMEM_B);
    cudaFuncSetAttribute(k_proj4,     cudaFuncAttributeMaxDynamicSharedMemorySize, SMEM_P);

    k_mask     <<<ROWS/8,       256>>>(mask);
    k_scan     <<<1,            256>>>();
    k_proj0    <<<dim3(32, 8),  256>>>(atom, Wai);
    k_pathprojm<<<PAIRS/64,     256, SMEM_B>>>(path, Wah, Wmh, bah);
    k_proj4    <<<dim3(256, 4), 256, SMEM_P>>>(Wah, Wmh);    // layer 1 projections
    k_attn     <<<ROWS,         256>>>(Wo, bo, bmh, 0);      // layer 1 -> g_atomh
    k_proj4    <<<dim3(256, 4), 256, SMEM_P>>>(Wah, Wmh);    // layer 2 projections
    k_attn     <<<ROWS,         256>>>(Wo, bo, bmh, 1);      // layer 2 -> g_cat
    k_final    <<<dim3(32, 4),  256>>>(Wao, bao, out);
}

// round 14
// speedup vs baseline: 2.3018x; 1.1582x over previous
#include <cuda_runtime.h>

// ---------------- problem constants ----------------
#define BB      32
#define NN      64
#define FA      82
#define FP      102
#define HH      8
#define DKK     80
#define HID     256
#define HB      (HH*BB)        // 256
#define ROWS    (BB*NN)        // 2048
#define PAIRS   (BB*NN*NN)     // 131072
#define CATK    722
#define CATS    724            // padded row stride for concat matrix
#define TPAD    68             // transposed-A smem row stride (16B multiple)

// ---------------- f32x2 packed helpers (sm_103a FFMA2) ----------------
__device__ __forceinline__ unsigned long long pk2(float x) {
    unsigned long long d;
    asm("mov.b64 %0, {%1, %1};" : "=l"(d) : "r"(__float_as_uint(x)));
    return d;
}
__device__ __forceinline__ unsigned long long ffma2(unsigned long long a,
                                                    unsigned long long b,
                                                    unsigned long long c) {
    unsigned long long d;
    asm("fma.rn.f32x2 %0, %1, %2, %3;" : "=l"(d) : "l"(a), "l"(b), "l"(c));
    return d;
}
__device__ __forceinline__ float2 upk2(unsigned long long d) {
    unsigned lo, hi;
    asm("mov.b64 {%0, %1}, %2;" : "=r"(lo), "=r"(hi) : "l"(d));
    return make_float2(__uint_as_float(lo), __uint_as_float(hi));
}

// ---------------- device scratch (no allocations allowed) ----------------
__device__ float g_Pc[(size_t)PAIRS*DKK];     // compacted: (path@W1p)+b_attn_h
__device__ float g_Qc[(size_t)PAIRS*DKK];     // compacted: path@W2p
__device__ float g_atom0[(size_t)HB*NN*DKK];  // atom_h0 [h*B+b, n, d]
__device__ float g_atomh[(size_t)HB*NN*DKK];  // current atom_h
__device__ float g_u [(size_t)HB*NN*DKK];
__device__ float g_v [(size_t)HB*NN*DKK];
__device__ float g_ws[(size_t)HB*NN*DKK];
__device__ float g_w [(size_t)HB*NN*DKK];
__device__ float g_cat[(size_t)ROWS*CATS];    // [atom_input | merged heads]
__device__ int   g_cnt[ROWS];
__device__ int   g_start[ROWS+1];
__device__ int   g_jidx[ROWS*NN];

// ============================================================
// Kernel M: per-(b,i) active-j list via warp ballot.
// ============================================================
__global__ void __launch_bounds__(256) k_mask(const float* __restrict__ mask) {
    const int bi = blockIdx.x * 8 + (threadIdx.x >> 5);
    const int lane = threadIdx.x & 31;
    const float m0 = mask[(size_t)bi*NN + lane];
    const float m1 = mask[(size_t)bi*NN + 32 + lane];
    const unsigned b0 = __ballot_sync(0xffffffffu, m0 != 0.f);
    const unsigned b1 = __ballot_sync(0xffffffffu, m1 != 0.f);
    const unsigned lt = (1u << lane) - 1u;
    const int c0 = __popc(b0);
    if (m0 != 0.f) g_jidx[bi*NN + __popc(b0 & lt)] = lane;
    if (m1 != 0.f) g_jidx[bi*NN + c0 + __popc(b1 & lt)] = lane + 32;
    if (lane == 0) g_cnt[bi] = c0 + __popc(b1);
}

// ============================================================
// Kernel S: exclusive prefix sum of g_cnt[2048] -> g_start. One CTA.
// ============================================================
__global__ void __launch_bounds__(256) k_scan() {
    __shared__ int warp_sums[8];
    __shared__ int warp_off[8];
    const int tid = threadIdx.x;
    const int base = tid * 8;
    int v[8]; int tot = 0;
#pragma unroll
    for (int i = 0; i < 8; i++) { v[i] = g_cnt[base + i]; tot += v[i]; }
    const int lane = tid & 31, wid = tid >> 5;
    int x = tot;
#pragma unroll
    for (int o = 1; o < 32; o <<= 1) {
        int y = __shfl_up_sync(0xffffffffu, x, o);
        if (lane >= o) x += y;
    }
    if (lane == 31) warp_sums[wid] = x;
    __syncthreads();
    if (tid == 0) {
        int a = 0;
#pragma unroll
        for (int w = 0; w < 8; w++) { warp_off[w] = a; a += warp_sums[w]; }
        g_start[ROWS] = a;
    }
    __syncthreads();
    int a = x - tot + warp_off[wid];
#pragma unroll
    for (int i = 0; i < 8; i++) { g_start[base + i] = a; a += v[i]; }
}

// ============================================================
// Kernel A: atom_h0 = atom_input @ W_atom_i (init g_atomh, g_cat[:, :82])
// ============================================================
__global__ void __launch_bounds__(256) k_proj0(const float* __restrict__ atom,
                                               const float* __restrict__ Wai) {
    __shared__ float As[64*FA];
    __shared__ float Bs[FA*DKK];
    const int tid = threadIdx.x;
    const int r0 = blockIdx.x * 64;
    const int h  = blockIdx.y;
    const int c0 = h * DKK;

    for (int i = tid; i < 64*FA; i += 256) As[i] = atom[(size_t)r0*FA + i];
    for (int i = tid; i < FA*DKK; i += 256) {
        int k = i / DKK, c = i % DKK;
        Bs[i] = Wai[(size_t)k*(HH*DKK) + c0 + c];
    }
    __syncthreads();

    const int ty = tid >> 4, tx = tid & 15;
    float acc[4][5];
#pragma unroll
    for (int r = 0; r < 4; r++)
#pragma unroll
        for (int c = 0; c < 5; c++) acc[r][c] = 0.f;

    for (int k = 0; k < FA; k++) {
        float a[4], b[5];
#pragma unroll
        for (int r = 0; r < 4; r++) a[r] = As[(ty*4+r)*FA + k];
#pragma unroll
        for (int c = 0; c < 5; c++) b[c] = Bs[k*DKK + tx*5 + c];
#pragma unroll
        for (int r = 0; r < 4; r++)
#pragma unroll
            for (int c = 0; c < 5; c++) acc[r][c] += a[r]*b[c];
    }

#pragma unroll
    for (int r = 0; r < 4; r++) {
        int row = r0 + ty*4 + r;
#pragma unroll
        for (int c = 0; c < 5; c++) {
            int d = tx*5 + c;
            size_t o = ((size_t)h*ROWS + row)*DKK + d;
            g_atom0[o] = acc[r][c];
            g_atomh[o] = acc[r][c];
        }
    }
    if (blockIdx.y == 0) {
        for (int i = tid; i < 64*FA; i += 256)
            g_cat[(size_t)(r0 + i/FA)*CATS + (i % FA)] = As[i];
    }
}

// ============================================================
// Kernel B': masked path projection. 64 slots x 160 cols, single pass,
// transposed-A smem, FFMA2, k+1 prefetch pipeline.
// __launch_bounds__(256, 2): 128-reg budget so the pipeline materializes.
// smem 93KB -> 2 CTAs/SM.
// ============================================================
__global__ void __launch_bounds__(256, 2) k_pathprojm(const float* __restrict__ path,
                                                      const float* __restrict__ Wah,
                                                      const float* __restrict__ Wmh,
                                                      const float* __restrict__ bah) {
    const int T = g_start[ROWS];
    const int t0 = blockIdx.x * 64;
    if (t0 >= T) return;

    extern __shared__ float sm[];
    float* At = sm;               // [FP][TPAD] transposed A (64 rows used)
    float* Bs = sm + FP*TPAD;     // [FP][160]
    __shared__ int sPair[64];

    const int tid = threadIdx.x;

    for (int i = tid; i < FP*160; i += 256) {
        int k = i / 160, c = i % 160;
        Bs[i] = (c < DKK) ? Wah[(size_t)(160+k)*DKK + c]
                          : Wmh[(size_t)(160+k)*DKK + (c - DKK)];
    }
    if (tid < 64) {
        int t = t0 + tid; if (t >= T) t = T - 1;
        int lo = 0, hi = ROWS - 1;
        while (lo < hi) {
            int mid = (lo + hi + 1) >> 1;
            if (__ldg(&g_start[mid]) <= t) lo = mid; else hi = mid - 1;
        }
        int slot = t - __ldg(&g_start[lo]);
        sPair[tid] = lo*NN + g_jidx[lo*NN + slot];
    }
    __syncthreads();

    // gather A rows transposed: 4 threads per row
    {
        const int row = tid >> 2, part = tid & 3;
        const float2* src = reinterpret_cast<const float2*>(path) + (size_t)sPair[row]*51;
        const int q0 = part*13;
        const int q1 = (part == 3) ? 51 : q0 + 13;
        for (int q = q0; q < q1; q++) {
            float2 v = src[q];
            At[(2*q)  *TPAD + row] = v.x;
            At[(2*q+1)*TPAD + row] = v.y;
        }
    }
    __syncthreads();

    const int ty = tid >> 4, tx = tid & 15;   // 4 rows x 10 cols per thread
    unsigned long long acc[4][5];
#pragma unroll
    for (int r = 0; r < 4; r++)
#pragma unroll
        for (int c = 0; c < 5; c++) acc[r][c] = 0ull;

    // software pipeline: prefetch k+1 while computing k
    float4 a_cur = *reinterpret_cast<const float4*>(At + 0*TPAD + ty*4);
    unsigned long long b_cur[5];
    {
        const unsigned long long* bp =
            reinterpret_cast<const unsigned long long*>(Bs + 0*160 + tx*10);
#pragma unroll
        for (int c = 0; c < 5; c++) b_cur[c] = bp[c];
    }

#pragma unroll 2
    for (int k = 0; k < FP; k++) {
        const int kn = (k + 1 < FP) ? k + 1 : k;   // in-bounds prefetch index
        const float4 a_nxt = *reinterpret_cast<const float4*>(At + kn*TPAD + ty*4);
        unsigned long long b_nxt[5];
        const unsigned long long* bp =
            reinterpret_cast<const unsigned long long*>(Bs + kn*160 + tx*10);
#pragma unroll
        for (int c = 0; c < 5; c++) b_nxt[c] = bp[c];

        const unsigned long long a0 = pk2(a_cur.x), a1 = pk2(a_cur.y),
                                 a2 = pk2(a_cur.z), a3 = pk2(a_cur.w);
#pragma unroll
        for (int c = 0; c < 5; c++) {
            acc[0][c] = ffma2(a0, b_cur[c], acc[0][c]);
            acc[1][c] = ffma2(a1, b_cur[c], acc[1][c]);
            acc[2][c] = ffma2(a2, b_cur[c], acc[2][c]);
            acc[3][c] = ffma2(a3, b_cur[c], acc[3][c]);
        }
        a_cur = a_nxt;
#pragma unroll
        for (int c = 0; c < 5; c++) b_cur[c] = b_nxt[c];
    }

#pragma unroll
    for (int r = 0; r < 4; r++) {
        int t = t0 + ty*4 + r;
        if (t >= T) continue;
#pragma unroll
        for (int c = 0; c < 5; c++) {
            const int col = tx*10 + 2*c;       // chunk never straddles col 80
            const float2 v = upk2(acc[r][c]);
            if (col < DKK) {
                g_Pc[(size_t)t*DKK + col]     = v.x + bah[col];
                g_Pc[(size_t)t*DKK + col + 1] = v.y + bah[col + 1];
            } else {
                g_Qc[(size_t)t*DKK + (col - DKK)]     = v.x;
                g_Qc[(size_t)t*DKK + (col - DKK) + 1] = v.y;
            }
        }
    }
}

// ============================================================
// Kernel P: {u,v,ws,w} = g_atomh @ {W1a,W1b,W2a,W2b} picked by blockIdx.y.
// Tile = 64 rows x 80 cols. smem 47.4KB -> 4 CTAs/SM. Grid (256, 4).
// ============================================================
__global__ void __launch_bounds__(256, 4) k_proj4(const float* __restrict__ Wah,
                                                  const float* __restrict__ Wmh) {
    extern __shared__ float sm[];
    float* At = sm;               // [DKK][TPAD] transposed A (64 rows used)
    float* Bs = sm + DKK*TPAD;    // [DKK][80]
    const int tid = threadIdx.x;
    const size_t r0 = (size_t)blockIdx.x * 64;
    const int y = blockIdx.y;     // 0:u(W1a) 1:v(W1b) 2:ws(W2a) 3:w(W2b)

    {
        const float* Wsrc = ((y < 2) ? Wah : Wmh) + (size_t)((y & 1) * 80) * DKK;
        for (int i = tid; i < DKK*80; i += 256) {
            int k = i / 80, c = i % 80;
            Bs[i] = Wsrc[(size_t)k*DKK + c];
        }
    }
    {
        const int row = tid >> 2, part = tid & 3;
        const float2* src = reinterpret_cast<const float2*>(g_atomh + (r0 + row)*DKK);
        const int q0 = part*10;
#pragma unroll
        for (int q = q0; q < q0 + 10; q++) {
            float2 v = src[q];
            At[(2*q)  *TPAD + row] = v.x;
            At[(2*q+1)*TPAD + row] = v.y;
        }
    }
    __syncthreads();

    const int tx  = tid & 7;      // 10 cols
    const int tyr = tid >> 3;     // 2 rows

    unsigned long long acc[2][5];
#pragma unroll
    for (int r = 0; r < 2; r++)
#pragma unroll
        for (int c = 0; c < 5; c++) acc[r][c] = 0ull;

#pragma unroll 2
    for (int k = 0; k < DKK; k++) {
        const float2 af = *reinterpret_cast<const float2*>(At + k*TPAD + tyr*2);
        const unsigned long long a0 = pk2(af.x), a1 = pk2(af.y);
        const unsigned long long* bp =
            reinterpret_cast<const unsigned long long*>(Bs + k*80 + tx*10);
        unsigned long long b[5];
#pragma unroll
        for (int c = 0; c < 5; c++) b[c] = bp[c];
#pragma unroll
        for (int c = 0; c < 5; c++) {
            acc[0][c] = ffma2(a0, b[c], acc[0][c]);
            acc[1][c] = ffma2(a1, b[c], acc[1][c]);
        }
    }

    float* dst = (y == 0) ? g_u : (y == 1) ? g_v : (y == 2) ? g_ws : g_w;
#pragma unroll
    for (int rr = 0; rr < 2; rr++) {
        const size_t row = r0 + tyr*2 + rr;
#pragma unroll
        for (int c = 0; c < 5; c++) {
            const int col = tx*10 + 2*c;
            const float2 v = upk2(acc[rr][c]);
            dst[row*DKK + col]     = v.x;
            dst[row*DKK + col + 1] = v.y;
        }
    }
}

// ============================================================
// Kernel C: message-passing layer over ACTIVE slots only. CTA=(b,i), warp=head.
// Both slot loops unrolled x4 (interleaved shuffle chains / MLP-12 loads).
// ============================================================
__global__ void __launch_bounds__(256) k_attn(const float* __restrict__ Wo,
                                              const float* __restrict__ bo,
                                              const float* __restrict__ bmsg,
                                              int mode) {
    __shared__ float sP[NN*DKK];
    __shared__ float sQ[NN*DKK];
    __shared__ float sSc[HH*NN];
    __shared__ float sPr[HH*NN];
    __shared__ int   sJ[NN];

    const int tid = threadIdx.x;
    const int bi = blockIdx.x;
    const int b = bi >> 6;
    const int cnt  = g_cnt[bi];
    const int base = g_start[bi];

    {
        const float4* ps = reinterpret_cast<const float4*>(g_Pc + (size_t)base*DKK);
        const float4* qs = reinterpret_cast<const float4*>(g_Qc + (size_t)base*DKK);
        float4* pd = reinterpret_cast<float4*>(sP);
        float4* qd = reinterpret_cast<float4*>(sQ);
        const int n4 = cnt * (DKK/4);
        for (int t = tid; t < n4; t += 256) { pd[t] = ps[t]; qd[t] = qs[t]; }
    }
    if (tid < cnt) sJ[tid] = g_jidx[bi*NN + tid];
    __syncthreads();

    const int h = tid >> 5, lane = tid & 31;
    const int hb = h*BB + b;
    const size_t base_i = ((size_t)hb*NN + (bi & 63))*DKK;

    const float* urow = g_u + base_i;
    const float u0 = urow[lane], u1 = urow[lane+32];
    const float u2 = (lane < 16) ? urow[64+lane] : 0.f;
    const float w0 = Wo[lane], w1 = Wo[lane+32];
    const float w2 = (lane < 16) ? Wo[64+lane] : 0.f;

    const float* V = g_v + (size_t)hb*NN*DKK;
    float* sc = sSc + h*NN;

    // ---- pass 1: scores, x4 unrolled (4 interleaved shuffle chains) ----
    int s = 0;
    for (; s + 3 < cnt; s += 4) {
        float sv[4];
#pragma unroll
        for (int r = 0; r < 4; r++) {
            const float* vr = V + (size_t)sJ[s+r]*DKK;
            float h0 = u0 + vr[lane]    + sP[(s+r)*DKK + lane];
            float h1 = u1 + vr[lane+32] + sP[(s+r)*DKK + 32 + lane];
            float h2 = 0.f;
            if (lane < 16) h2 = u2 + vr[64+lane] + sP[(s+r)*DKK + 64 + lane];
            h0 = h0 > 0.f ? h0 : 0.2f*h0;
            h1 = h1 > 0.f ? h1 : 0.2f*h1;
            h2 = h2 > 0.f ? h2 : 0.2f*h2;
            sv[r] = h0*w0 + h1*w1 + h2*w2;
        }
#pragma unroll
        for (int o = 16; o >= 1; o >>= 1) {
#pragma unroll
            for (int r = 0; r < 4; r++)
                sv[r] += __shfl_xor_sync(0xffffffffu, sv[r], o);
        }
        if (lane == 0) {
            sc[s] = sv[0]; sc[s+1] = sv[1]; sc[s+2] = sv[2]; sc[s+3] = sv[3];
        }
    }
    for (; s < cnt; s++) {
        const float* vr = V + (size_t)sJ[s]*DKK;
        float h0 = u0 + vr[lane]    + sP[s*DKK + lane];
        float h1 = u1 + vr[lane+32] + sP[s*DKK + 32 + lane];
        float h2 = 0.f;
        if (lane < 16) h2 = u2 + vr[64+lane] + sP[s*DKK + 64 + lane];
        h0 = h0 > 0.f ? h0 : 0.2f*h0;
        h1 = h1 > 0.f ? h1 : 0.2f*h1;
        h2 = h2 > 0.f ? h2 : 0.2f*h2;
        float sv = h0*w0 + h1*w1 + h2*w2;
#pragma unroll
        for (int o = 16; o >= 1; o >>= 1) sv += __shfl_xor_sync(0xffffffffu, sv, o);
        if (lane == 0) sc[s] = sv;
    }
    __syncwarp();

    // ---- masked softmax (masked scores are exactly 0) ----
    const float bov = bo[0];
    float s0 = (lane      < cnt) ? sc[lane]      + bov : -1e30f;
    float s1 = (lane + 32 < cnt) ? sc[lane + 32] + bov : -1e30f;
    float mx = fmaxf(s0, s1);
#pragma unroll
    for (int o = 16; o >= 1; o >>= 1) mx = fmaxf(mx, __shfl_xor_sync(0xffffffffu, mx, o));
    if (cnt < NN) mx = fmaxf(mx, 0.f);
    float e0 = (lane      < cnt) ? __expf(s0 - mx) : 0.f;
    float e1 = (lane + 32 < cnt) ? __expf(s1 - mx) : 0.f;
    float tot = e0 + e1;
#pragma unroll
    for (int o = 16; o >= 1; o >>= 1) tot += __shfl_xor_sync(0xffffffffu, tot, o);
    const float inv = 1.f / (tot + 1e-20f);
    sPr[h*NN + lane]      = e0 * inv;
    sPr[h*NN + lane + 32] = e1 * inv;
    const float S = tot * inv;
    __syncwarp();

    // ---- pass 2: weighted message accumulation, x4 unrolled ----
    const float* W_ = g_w + (size_t)hb*NN*DKK;
    const float* pr = sPr + h*NN;
    float a0 = 0.f, a1 = 0.f, a2 = 0.f;
    s = 0;
    for (; s + 3 < cnt; s += 4) {
#pragma unroll
        for (int r = 0; r < 4; r++) {
            const float p = pr[s+r];
            const float* wr = W_ + (size_t)sJ[s+r]*DKK;
            a0 += p * (wr[lane]    + sQ[(s+r)*DKK + lane]);
            a1 += p * (wr[lane+32] + sQ[(s+r)*DKK + 32 + lane]);
            if (lane < 16) a2 += p * (wr[64+lane] + sQ[(s+r)*DKK + 64 + lane]);
        }
    }
    for (; s < cnt; s++) {
        const float p = pr[s];
        const float* wr = W_ + (size_t)sJ[s]*DKK;
        a0 += p * (wr[lane]    + sQ[s*DKK + lane]);
        a1 += p * (wr[lane+32] + sQ[s*DKK + 32 + lane]);
        if (lane < 16) a2 += p * (wr[64+lane] + sQ[s*DKK + 64 + lane]);
    }

    const float* wsr = g_ws   + base_i;
    const float* a0r = g_atom0 + base_i;
    float n0 = fmaxf(S*wsr[lane]    + a0 + bmsg[lane]    + a0r[lane],    0.f);
    float n1 = fmaxf(S*wsr[lane+32] + a1 + bmsg[lane+32] + a0r[lane+32], 0.f);
    float n2 = 0.f;
    if (lane < 16) n2 = fmaxf(S*wsr[64+lane] + a2 + bmsg[64+lane] + a0r[64+lane], 0.f);

    if (mode == 0) {
        float* o = g_atomh + base_i;
        o[lane] = n0; o[lane+32] = n1; if (lane < 16) o[64+lane] = n2;
    } else {
        float* o = g_cat + (size_t)bi*CATS + FA + h*DKK;
        o[lane] = n0; o[lane+32] = n1; if (lane < 16) o[64+lane] = n2;
    }
}

// ============================================================
// Kernel E: out = relu(g_cat[2048,722] @ W_atom_o[722,256] + b)
// Transposed-A smem + FFMA2 + global->reg->smem chunk pipeline:
// next chunk's tiles are loaded into registers BEFORE computing the
// current chunk, overlapping DRAM/L2 latency with the FFMA2 stream.
// ============================================================
__global__ void __launch_bounds__(256) k_final(const float* __restrict__ Wao,
                                               const float* __restrict__ bao,
                                               float* __restrict__ out) {
    __shared__ float At[64*TPAD];   // transposed A chunk [k][r]
    __shared__ float Bs[64*64];
    const int tid = threadIdx.x;
    const int r0 = blockIdx.x * 64;
    const int c0 = blockIdx.y * 64;
    const int ty = tid >> 4, tx = tid & 15;
    const int NCH = (CATK + 63) / 64;   // 12 chunks

    unsigned long long acc[4][2];
#pragma unroll
    for (int r = 0; r < 4; r++) { acc[r][0] = 0ull; acc[r][1] = 0ull; }

    float aReg[16], bReg[16];
    // prologue: load chunk 0 into registers
    {
        const int kc = (CATK < 64) ? CATK : 64;
#pragma unroll
        for (int i = 0; i < 16; i++) {
            const int t = tid + i*256;
            const int r = t >> 6, k = t & 63;
            aReg[i] = (k < kc) ? g_cat[(size_t)(r0 + r)*CATS + k] : 0.f;
        }
#pragma unroll
        for (int i = 0; i < 16; i++) {
            const int t = tid + i*256;
            const int k = t >> 6, c = t & 63;
            bReg[i] = (k < kc) ? Wao[(size_t)k*HID + c0 + c] : 0.f;
        }
    }

    for (int ch = 0; ch < NCH; ch++) {
        __syncthreads();   // previous compute done -> safe to overwrite smem
        // store staged registers to smem
#pragma unroll
        for (int i = 0; i < 16; i++) {
            const int t = tid + i*256;
            const int r = t >> 6, k = t & 63;
            At[k*TPAD + r] = aReg[i];
        }
#pragma unroll
        for (int i = 0; i < 16; i++) {
            const int t = tid + i*256;
            Bs[t] = bReg[i];
        }
        __syncthreads();

        // issue next chunk's global loads (overlap with compute below)
        if (ch + 1 < NCH) {
            const int k0 = (ch + 1) * 64;
            const int kc = (CATK - k0 < 64) ? (CATK - k0) : 64;
#pragma unroll
            for (int i = 0; i < 16; i++) {
                const int t = tid + i*256;
                const int r = t >> 6, k = t & 63;
                aReg[i] = (k < kc) ? g_cat[(size_t)(r0 + r)*CATS + k0 + k] : 0.f;
            }
#pragma unroll
            for (int i = 0; i < 16; i++) {
                const int t = tid + i*256;
                const int k = t >> 6, c = t & 63;
                bReg[i] = (k < kc) ? Wao[(size_t)(k0 + k)*HID + c0 + c] : 0.f;
            }
        }

        // compute current chunk from smem
#pragma unroll 8
        for (int k = 0; k < 64; k++) {
            const float4 av = *reinterpret_cast<const float4*>(At + k*TPAD + ty*4);
            const unsigned long long* bp =
                reinterpret_cast<const unsigned long long*>(Bs + k*64 + tx*4);
            const unsigned long long b01 = bp[0], b23 = bp[1];
            const unsigned long long a0 = pk2(av.x), a1 = pk2(av.y),
                                     a2 = pk2(av.z), a3 = pk2(av.w);
            acc[0][0] = ffma2(a0, b01, acc[0][0]); acc[0][1] = ffma2(a0, b23, acc[0][1]);
            acc[1][0] = ffma2(a1, b01, acc[1][0]); acc[1][1] = ffma2(a1, b23, acc[1][1]);
            acc[2][0] = ffma2(a2, b01, acc[2][0]); acc[2][1] = ffma2(a2, b23, acc[2][1]);
            acc[3][0] = ffma2(a3, b01, acc[3][0]); acc[3][1] = ffma2(a3, b23, acc[3][1]);
        }
    }

#pragma unroll
    for (int r = 0; r < 4; r++) {
        int row = r0 + ty*4 + r;
        const float2 v01 = upk2(acc[r][0]);
        const float2 v23 = upk2(acc[r][1]);
        const int col = c0 + tx*4;
        out[(size_t)row*HID + col    ] = fmaxf(v01.x + bao[col    ], 0.f);
        out[(size_t)row*HID + col + 1] = fmaxf(v01.y + bao[col + 1], 0.f);
        out[(size_t)row*HID + col + 2] = fmaxf(v23.x + bao[col + 2], 0.f);
        out[(size_t)row*HID + col + 3] = fmaxf(v23.y + bao[col + 3], 0.f);
    }
}

// ============================================================
extern "C" void kernel_launch(void* const* d_in, const int* in_sizes, int n_in,
                              void* d_out, int out_size) {
    const float* atom = (const float*)d_in[0];
    const float* path = (const float*)d_in[1];
    const float* mask = (const float*)d_in[2];
    const float* Wai  = (const float*)d_in[3];
    const float* Wah  = (const float*)d_in[4];
    const float* bah  = (const float*)d_in[5];
    const float* Wo   = (const float*)d_in[6];
    const float* bo   = (const float*)d_in[7];
    const float* Wmh  = (const float*)d_in[8];
    const float* bmh  = (const float*)d_in[9];
    const float* Wao  = (const float*)d_in[10];
    const float* bao  = (const float*)d_in[11];
    float* out = (float*)d_out;

    const int SMEM_B = (FP*TPAD  + FP*160) * 4;   //  93,024 B -> 2 CTAs/SM
    const int SMEM_P = (DKK*TPAD + DKK*80) * 4;   //  47,360 B -> 4 CTAs/SM
    cudaFuncSetAttribute(k_pathprojm, cudaFuncAttributeMaxDynamicSharedMemorySize, SMEM_B);
    cudaFuncSetAttribute(k_proj4,     cudaFuncAttributeMaxDynamicSharedMemorySize, SMEM_P);

    k_mask     <<<ROWS/8,       256>>>(mask);
    k_scan     <<<1,            256>>>();
    k_proj0    <<<dim3(32, 8),  256>>>(atom, Wai);
    k_pathprojm<<<PAIRS/64,     256, SMEM_B>>>(path, Wah, Wmh, bah);
    k_proj4    <<<dim3(256, 4), 256, SMEM_P>>>(Wah, Wmh);    // layer 1 projections
    k_attn     <<<ROWS,         256>>>(Wo, bo, bmh, 0);      // layer 1 -> g_atomh
    k_proj4    <<<dim3(256, 4), 256, SMEM_P>>>(Wah, Wmh);    // layer 2 projections
    k_attn     <<<ROWS,         256>>>(Wo, bo, bmh, 1);      // layer 2 -> g_cat
    k_final    <<<dim3(32, 4),  256>>>(Wao, bao, out);
}